// round 12
// baseline (speedup 1.0000x reference)
#include <cuda_runtime.h>
#include <cuda_bf16.h>
#include <stdint.h>

#define SEQ   2048
#define BATCH 4
#define NH    16
#define HD    64
#define DIMM  1024
#define GK    3072          // tripled K for compensated bf16
#define MTOT  8192
#define NKB   (GK/32)       // 96 k-blocks of 32

typedef __nv_bfloat16 bf16;

// ---------------- scratch (__device__ globals; referenced ONLY in device code)
__device__ bf16 g_q   [(size_t)64*SEQ*192];      // [bh][s][qh|ql|qh], pre-scaled
__device__ bf16 g_k   [(size_t)64*SEQ*192];      // [bh][s][kh|kh|kl]
__device__ bf16 g_v   [(size_t)64*2*SEQ*64];     // [bh][plane hi/lo][s][d]
__device__ bf16 g_Ax  [(size_t)MTOT*GK];         // split activations (x, later attn out)
__device__ bf16 g_Bqkv[(size_t)3072*GK];         // split+transposed w_qkv
__device__ bf16 g_Bout[(size_t)1024*GK];         // split+transposed w_out

// ---------------- small helpers ---------------------------------------------
__device__ __forceinline__ uint32_t smem_u32(const void* p) {
    uint32_t a;
    asm("{ .reg .u64 t; cvta.to.shared.u64 t, %1; cvt.u32.u64 %0, t; }"
        : "=r"(a) : "l"(p));
    return a;
}
// pack2(lo, hi): memory order [lo, hi]
__device__ __forceinline__ uint32_t pack2(float lo, float hi) {
    uint32_t r;
    asm("cvt.rn.bf16x2.f32 %0, %1, %2;" : "=r"(r) : "f"(hi), "f"(lo));
    return r;
}
__device__ __forceinline__ float lo_f(uint32_t x) { return __uint_as_float(x << 16); }
__device__ __forceinline__ float hi_f(uint32_t x) { return __uint_as_float(x & 0xffff0000u); }

__device__ __forceinline__ void ldsm_x4(uint32_t* r, uint32_t addr) {
    asm volatile("ldmatrix.sync.aligned.m8n8.x4.shared.b16 {%0,%1,%2,%3}, [%4];"
        : "=r"(r[0]), "=r"(r[1]), "=r"(r[2]), "=r"(r[3]) : "r"(addr));
}
__device__ __forceinline__ void ldsm_x4_t(uint32_t* r, uint32_t addr) {
    asm volatile("ldmatrix.sync.aligned.m8n8.x4.trans.shared.b16 {%0,%1,%2,%3}, [%4];"
        : "=r"(r[0]), "=r"(r[1]), "=r"(r[2]), "=r"(r[3]) : "r"(addr));
}
__device__ __forceinline__ void mma_bf16(float* d, const uint32_t* a, const uint32_t* b) {
    asm volatile(
        "mma.sync.aligned.m16n8k16.row.col.f32.bf16.bf16.f32 "
        "{%0,%1,%2,%3}, {%4,%5,%6,%7}, {%8,%9}, {%0,%1,%2,%3};"
        : "+f"(d[0]), "+f"(d[1]), "+f"(d[2]), "+f"(d[3])
        : "r"(a[0]), "r"(a[1]), "r"(a[2]), "r"(a[3]), "r"(b[0]), "r"(b[1]));
}
__device__ __forceinline__ void cp16(uint32_t s, const void* g) {
    asm volatile("cp.async.cg.shared.global [%0], [%1], 16;" :: "r"(s), "l"(g));
}
#define CP_COMMIT()  asm volatile("cp.async.commit_group;" ::: "memory")
#define CP_WAIT1()   asm volatile("cp.async.wait_group 1;" ::: "memory")
#define CP_WAIT0()   asm volatile("cp.async.wait_group 0;" ::: "memory")

__device__ __forceinline__ void split_bf16(float v, bf16& hi, bf16& lo) {
    hi = __float2bfloat16(v);
    lo = __float2bfloat16(v - __bfloat162float(hi));
}

// ---------------- conversion kernels ----------------------------------------
__global__ __launch_bounds__(256) void conv_split_kernel(const float* __restrict__ in)
{
    int idx = blockIdx.x * 256 + threadIdx.x;
    int m  = idx >> 8;
    int c4 = (idx & 255) << 2;
    float4 v = *(const float4*)(in + (size_t)m * DIMM + c4);
    bf16 h[4], l[4];
    split_bf16(v.x, h[0], l[0]); split_bf16(v.y, h[1], l[1]);
    split_bf16(v.z, h[2], l[2]); split_bf16(v.w, h[3], l[3]);
    size_t ro = (size_t)m * GK + c4;
    *(uint2*)(g_Ax + ro)        = *(uint2*)h;
    *(uint2*)(g_Ax + ro + 1024) = *(uint2*)l;
    *(uint2*)(g_Ax + ro + 2048) = *(uint2*)h;
}

// w[k][n] f32 -> B'[n][0:3072] bf16 = [hi | hi | lo]  (transpose + split)
__global__ void conv_w_kernel(const float* __restrict__ w, int N, int which)
{
    __shared__ float tile[32][33];
    bf16* outB = which ? g_Bout : g_Bqkv;
    int tx = threadIdx.x, ty = threadIdx.y;
    int k0 = blockIdx.x * 32, n0 = blockIdx.y * 32;
    tile[ty][tx] = w[(size_t)(k0 + ty) * N + n0 + tx];
    __syncthreads();
    float v = tile[tx][ty];
    int n = n0 + ty, k = k0 + tx;
    bf16 hi, lo;
    split_bf16(v, hi, lo);
    size_t ro = (size_t)n * GK + k;
    outB[ro]        = hi;
    outB[ro + 1024] = hi;
    outB[ro + 2048] = lo;
}

// ---------------- mma.sync GEMM: 128x128, warp 64x32, BK=32 (R11, frozen) ----
#define A_STG  10240                       // 128 x 40 bf16
#define G_SMEM (6 * A_STG)                 // 3 A stages + 3 B stages

__global__ __launch_bounds__(256, 1) void mma_gemm_kernel(const float* __restrict__ bias,
                                                          float* __restrict__ Cout,
                                                          int mode)
{
    extern __shared__ __align__(16) char gsm[];
    const uint32_t aBase = smem_u32(gsm);
    const uint32_t bBase = aBase + 3 * A_STG;
    const uint32_t aS[3] = { aBase, aBase + A_STG, aBase + 2*A_STG };
    const uint32_t bS[3] = { bBase, bBase + A_STG, bBase + 2*A_STG };

    const bf16* A = g_Ax;
    const bf16* B = mode ? g_Bout : g_Bqkv;

    const int t    = threadIdx.x;
    const int wid  = t >> 5;
    const int lane = t & 31;
    const int warp_m = wid & 1;
    const int warp_n = wid >> 1;
    const int n0 = blockIdx.x * 128;
    const int m0 = blockIdx.y * 128;

    const int lrow = t >> 1;
    const int lseg = (t & 1) * 16;
    const bf16* Ap = A + (size_t)(m0 + lrow) * GK + lseg;
    const bf16* Bp = B + (size_t)(n0 + lrow) * GK + lseg;
    const uint32_t sOff = (uint32_t)(lrow * 40 + lseg) * 2;

    const uint32_t aLd = (uint32_t)(((warp_m*64 + (lane & 15)) * 40) + (lane >> 4) * 8) * 2;
    const uint32_t bLd = (uint32_t)(((warp_n*32 + (lane >> 4)*8 + (lane & 7)) * 40)
                                    + ((lane >> 3) & 1) * 8) * 2;

    float acc[4][4][4];
#pragma unroll
    for (int i = 0; i < 4; i++)
#pragma unroll
        for (int j = 0; j < 4; j++)
#pragma unroll
            for (int q = 0; q < 4; q++) acc[i][j][q] = 0.0f;

    uint32_t afr[2][4][4];
    uint32_t bfr[2][4][2];

    auto load_frags = [&](int buf, uint32_t ab, uint32_t bb, int k0) {
#pragma unroll
        for (int mt = 0; mt < 4; mt++)
            ldsm_x4(afr[buf][mt], ab + aLd + (uint32_t)(mt*16*40 + k0) * 2);
#pragma unroll
        for (int ntp = 0; ntp < 4; ntp += 2) {
            uint32_t tmp[4];
            ldsm_x4(tmp, bb + bLd + (uint32_t)(ntp*8*40 + k0) * 2);
            bfr[buf][ntp][0] = tmp[0];   bfr[buf][ntp][1] = tmp[1];
            bfr[buf][ntp+1][0] = tmp[2]; bfr[buf][ntp+1][1] = tmp[3];
        }
    };
    auto hmma_block = [&](int buf) {
#pragma unroll
        for (int mt = 0; mt < 4; mt++)
#pragma unroll
            for (int nt = 0; nt < 4; nt++)
                mma_bf16(acc[mt][nt], afr[buf][mt], bfr[buf][nt]);
    };
    auto issue_cp = [&](int kb, int s) {
        const bf16* Ak = Ap + kb * 32;
        const bf16* Bk = Bp + kb * 32;
        cp16(aS[s] + sOff, Ak);  cp16(aS[s] + sOff + 16, Ak + 8);
        cp16(bS[s] + sOff, Bk);  cp16(bS[s] + sOff + 16, Bk + 8);
        CP_COMMIT();
    };

    // prologue: stages 0,1 <- k-blocks 0,1
    issue_cp(0, 0);
    issue_cp(1, 1);
    CP_WAIT1();
    __syncthreads();
    load_frags(0, aS[0], bS[0], 0);

#define GSTEP(KB, S0, S1, S2) do {                                          \
        load_frags(1, aS[S0], bS[S0], 16);                                  \
        hmma_block(0);                                                      \
        if ((KB) + 2 < NKB) issue_cp((KB) + 2, (S2));                       \
        hmma_block(1);                                                      \
        if ((KB) + 1 < NKB) {                                               \
            if ((KB) + 2 < NKB) CP_WAIT1(); else CP_WAIT0();                \
            __syncthreads();                                                \
            load_frags(0, aS[S1], bS[S1], 0);                               \
        }                                                                   \
    } while (0)

    for (int kb3 = 0; kb3 < NKB; kb3 += 3) {
        GSTEP(kb3 + 0, 0, 1, 2);
        GSTEP(kb3 + 1, 1, 2, 0);
        GSTEP(kb3 + 2, 2, 0, 1);
    }
#undef GSTEP

    // ---------------- epilogue ----------------
#pragma unroll
    for (int mt = 0; mt < 4; mt++) {
#pragma unroll
        for (int nt = 0; nt < 4; nt++) {
            int m_lo = m0 + warp_m*64 + mt*16 + (lane >> 2);
            int n    = n0 + warp_n*32 + nt*8 + 2*(lane & 3);
#pragma unroll
            for (int half = 0; half < 2; half++) {
                int m = m_lo + half * 8;
                float v0 = acc[mt][nt][half*2 + 0];
                float v1 = acc[mt][nt][half*2 + 1];
                if (mode == 1) {
                    float2 bi = *(const float2*)&bias[n];
                    *(float2*)&Cout[(size_t)m * DIMM + n] =
                        make_float2(v0 + bi.x, v1 + bi.y);
                } else {
                    int part = n >> 10, h = (n >> 6) & 15, d = n & 63;
                    int b = m >> 11, s = m & 2047;
                    int bh = b * NH + h;
                    if (part == 0) { v0 *= 0.125f; v1 *= 0.125f; }
                    uint32_t h2 = pack2(v0, v1);
                    uint32_t l2 = pack2(v0 - lo_f(h2), v1 - hi_f(h2));
                    if (part == 0) {          // Q: [hi | lo | hi], pre-scaled
                        size_t base = ((size_t)bh * SEQ + s) * 192 + d;
                        *(uint32_t*)&g_q[base]       = h2;
                        *(uint32_t*)&g_q[base + 64]  = l2;
                        *(uint32_t*)&g_q[base + 128] = h2;
                    } else if (part == 1) {   // K: [hi | hi | lo]
                        size_t base = ((size_t)bh * SEQ + s) * 192 + d;
                        *(uint32_t*)&g_k[base]       = h2;
                        *(uint32_t*)&g_k[base + 64]  = h2;
                        *(uint32_t*)&g_k[base + 128] = l2;
                    } else {                  // V: planes hi / lo
                        size_t base = (((size_t)bh * 2) * SEQ + s) * 64 + d;
                        *(uint32_t*)&g_v[base]                 = h2;
                        *(uint32_t*)&g_v[base + (size_t)SEQ*64] = l2;
                    }
                }
            }
        }
    }
}

// ---------------- flash attention: ldsm double-buffered S and PV loops -------
__global__ __launch_bounds__(256) void attn_mma_kernel()
{
    __shared__ __align__(16) bf16 Ks[64][200];
    __shared__ __align__(16) bf16 Vh[64][72];
    __shared__ __align__(16) bf16 Vl[64][72];

    const int t    = threadIdx.x;
    const int wid  = t >> 5;
    const int lane = t & 31;
    const int bh   = blockIdx.y;
    const int q0   = blockIdx.x * 128;

    const bf16* Qg = g_q + (size_t)bh * SEQ * 192;
    const bf16* Kg = g_k + (size_t)bh * SEQ * 192;
    const bf16* Vg = g_v + (size_t)bh * 2 * SEQ * 64;

    const uint32_t ksBase = smem_u32(&Ks[0][0]);
    const uint32_t vhBase = smem_u32(&Vh[0][0]);
    const uint32_t vlBase = smem_u32(&Vl[0][0]);

    // per-lane invariant parts of ldsm addresses
    const uint32_t kRow = (uint32_t)((lane >> 4)*8 + (lane & 7)) * 200
                        + (uint32_t)((lane >> 3) & 1) * 8;     // + p*16*200 + ks*16
    const uint32_t vRow = (uint32_t)(lane & 15) * 72
                        + (uint32_t)(lane >> 4) * 8;           // + kt*16*72 + p*16

    // ---- Q A-fragments directly from gmem (one-time) ----
    uint32_t qfr[12][4];
    {
        const bf16* Qr = Qg + (size_t)(q0 + 16*wid + (lane >> 2)) * 192 + (lane & 3) * 2;
#pragma unroll
        for (int ks = 0; ks < 12; ks++) {
            qfr[ks][0] = *(const uint32_t*)(Qr + ks*16);
            qfr[ks][1] = *(const uint32_t*)(Qr + 8*192 + ks*16);
            qfr[ks][2] = *(const uint32_t*)(Qr + ks*16 + 8);
            qfr[ks][3] = *(const uint32_t*)(Qr + 8*192 + ks*16 + 8);
        }
    }

    float acc_o[8][4];
#pragma unroll
    for (int i = 0; i < 8; i++)
#pragma unroll
        for (int j = 0; j < 4; j++) acc_o[i][j] = 0.0f;
    float m_lo = -1e30f, m_hi = -1e30f, l_lo = 0.0f, l_hi = 0.0f;

    for (int j0 = 0; j0 < SEQ; j0 += 64) {
        __syncthreads();                  // previous tile fully consumed
#pragma unroll
        for (int i = 0; i < 6; i++) {
            int idx = t + i * 256;        // 1536 8-elem chunks
            int r = idx / 24, c = idx % 24;
            *(uint4*)&Ks[r][c*8] =
                *(const uint4*)(Kg + (size_t)(j0 + r) * 192 + c*8);
        }
#pragma unroll
        for (int i = 0; i < 2; i++) {
            int idx = t + i * 256;        // 512
            int r = idx / 8, c = idx % 8;
            *(uint4*)&Vh[r][c*8] =
                *(const uint4*)(Vg + (size_t)(j0 + r) * 64 + c*8);
            *(uint4*)&Vl[r][c*8] =
                *(const uint4*)(Vg + (size_t)SEQ*64 + (size_t)(j0 + r) * 64 + c*8);
        }
        __syncthreads();

        // ---- S = Q' @ K'^T  (d'=192), K-fragment double buffering ----
        float sc[8][4];
#pragma unroll
        for (int i = 0; i < 8; i++)
#pragma unroll
            for (int j = 0; j < 4; j++) sc[i][j] = 0.0f;

        uint32_t kf[2][4][4];
#pragma unroll
        for (int p = 0; p < 4; p++)
            ldsm_x4(kf[0][p], ksBase + (kRow + (uint32_t)(p*16*200)) * 2);

#pragma unroll
        for (int ks = 0; ks < 12; ks++) {
            const int cur = ks & 1, nxt = cur ^ 1;
            if (ks + 1 < 12) {
#pragma unroll
                for (int p = 0; p < 4; p++)
                    ldsm_x4(kf[nxt][p],
                            ksBase + (kRow + (uint32_t)(p*16*200 + (ks+1)*16)) * 2);
            }
#pragma unroll
            for (int p = 0; p < 4; p++) {
                mma_bf16(sc[2*p],   qfr[ks], kf[cur][p]);
                mma_bf16(sc[2*p+1], qfr[ks], kf[cur][p] + 2);
            }
        }

        // ---- online softmax (rows: lane>>2 and +8) ----
        float mx0 = -1e30f, mx1 = -1e30f;
#pragma unroll
        for (int nt = 0; nt < 8; nt++) {
            mx0 = fmaxf(mx0, fmaxf(sc[nt][0], sc[nt][1]));
            mx1 = fmaxf(mx1, fmaxf(sc[nt][2], sc[nt][3]));
        }
        mx0 = fmaxf(mx0, __shfl_xor_sync(0xffffffffu, mx0, 1));
        mx0 = fmaxf(mx0, __shfl_xor_sync(0xffffffffu, mx0, 2));
        mx1 = fmaxf(mx1, __shfl_xor_sync(0xffffffffu, mx1, 1));
        mx1 = fmaxf(mx1, __shfl_xor_sync(0xffffffffu, mx1, 2));
        float mn0 = fmaxf(m_lo, mx0), mn1 = fmaxf(m_hi, mx1);
        float f0 = __expf(m_lo - mn0), f1 = __expf(m_hi - mn1);
        m_lo = mn0; m_hi = mn1;

        float s0 = 0.0f, s1 = 0.0f;
#pragma unroll
        for (int nt = 0; nt < 8; nt++) {
            sc[nt][0] = __expf(sc[nt][0] - mn0); s0 += sc[nt][0];
            sc[nt][1] = __expf(sc[nt][1] - mn0); s0 += sc[nt][1];
            sc[nt][2] = __expf(sc[nt][2] - mn1); s1 += sc[nt][2];
            sc[nt][3] = __expf(sc[nt][3] - mn1); s1 += sc[nt][3];
        }
        s0 += __shfl_xor_sync(0xffffffffu, s0, 1);
        s0 += __shfl_xor_sync(0xffffffffu, s0, 2);
        s1 += __shfl_xor_sync(0xffffffffu, s1, 1);
        s1 += __shfl_xor_sync(0xffffffffu, s1, 2);
        l_lo = l_lo * f0 + s0;
        l_hi = l_hi * f1 + s1;
#pragma unroll
        for (int nt = 0; nt < 8; nt++) {
            acc_o[nt][0] *= f0; acc_o[nt][1] *= f0;
            acc_o[nt][2] *= f1; acc_o[nt][3] *= f1;
        }

        // ---- P fragments (C-layout == A-frag layout) ----
        uint32_t aph[4][4], apl[4][4];
#pragma unroll
        for (int kt = 0; kt < 4; kt++) {
            aph[kt][0] = pack2(sc[2*kt][0],   sc[2*kt][1]);
            aph[kt][1] = pack2(sc[2*kt][2],   sc[2*kt][3]);
            aph[kt][2] = pack2(sc[2*kt+1][0], sc[2*kt+1][1]);
            aph[kt][3] = pack2(sc[2*kt+1][2], sc[2*kt+1][3]);
            apl[kt][0] = pack2(sc[2*kt][0]   - lo_f(aph[kt][0]), sc[2*kt][1]   - hi_f(aph[kt][0]));
            apl[kt][1] = pack2(sc[2*kt][2]   - lo_f(aph[kt][1]), sc[2*kt][3]   - hi_f(aph[kt][1]));
            apl[kt][2] = pack2(sc[2*kt+1][0] - lo_f(aph[kt][2]), sc[2*kt+1][1] - hi_f(aph[kt][2]));
            apl[kt][3] = pack2(sc[2*kt+1][2] - lo_f(aph[kt][3]), sc[2*kt+1][3] - hi_f(aph[kt][3]));
        }

        // ---- O += P @ V, V-fragment double buffering (16 flat steps) ----
        uint32_t vb[2][8];
        {
            uint32_t voff0 = vRow * 2;
            ldsm_x4_t(vb[0],     vhBase + voff0);
            ldsm_x4_t(vb[0] + 4, vlBase + voff0);
        }
#pragma unroll
        for (int step = 0; step < 16; step++) {
            const int cur = step & 1, nxt = cur ^ 1;
            if (step + 1 < 16) {
                int kt1 = (step + 1) >> 2, p1 = (step + 1) & 3;
                uint32_t voff = (vRow + (uint32_t)(kt1*16*72 + p1*16)) * 2;
                ldsm_x4_t(vb[nxt],     vhBase + voff);
                ldsm_x4_t(vb[nxt] + 4, vlBase + voff);
            }
            const int kt = step >> 2, ntp = (step & 3) * 2;
            const uint32_t* bh4 = vb[cur];
            const uint32_t* bl4 = vb[cur] + 4;
            mma_bf16(acc_o[ntp],   aph[kt], bh4);
            mma_bf16(acc_o[ntp],   apl[kt], bh4);
            mma_bf16(acc_o[ntp],   aph[kt], bl4);
            mma_bf16(acc_o[ntp+1], aph[kt], bh4 + 2);
            mma_bf16(acc_o[ntp+1], apl[kt], bh4 + 2);
            mma_bf16(acc_o[ntp+1], aph[kt], bl4 + 2);
        }
    }

    // ---- finalize: reference reshape semantics (flat view of [B,H,S,D]):
    //   (b,h,s,d) -> row b*2048 + h*128 + (s>>4), col (s&15)*64 + d
    float inv0 = 1.0f / l_lo, inv1 = 1.0f / l_hi;
    const int b = bh >> 4, h = bh & 15;
    const int s_base = q0 + 16*wid + (lane >> 2);
#pragma unroll
    for (int nt = 0; nt < 8; nt++) {
        int d = nt*8 + 2*(lane & 3);
#pragma unroll
        for (int half = 0; half < 2; half++) {
            int s = s_base + half * 8;
            int m   = b * 2048 + h * 128 + (s >> 4);
            int col = (s & 15) * 64 + d;
            float v0 = acc_o[nt][half*2 + 0] * (half ? inv1 : inv0);
            float v1 = acc_o[nt][half*2 + 1] * (half ? inv1 : inv0);
            uint32_t h2 = pack2(v0, v1);
            uint32_t l2 = pack2(v0 - lo_f(h2), v1 - hi_f(h2));
            size_t base = (size_t)m * GK + col;
            *(uint32_t*)&g_Ax[base]        = h2;
            *(uint32_t*)&g_Ax[base + 1024] = l2;
            *(uint32_t*)&g_Ax[base + 2048] = h2;
        }
    }
}

// ---------------------------------------------------------------------------
extern "C" void kernel_launch(void* const* d_in, const int* in_sizes, int n_in,
                              void* d_out, int out_size)
{
    const float* x     = (const float*)d_in[0];
    const float* w_qkv = (const float*)d_in[1];
    const float* w_out = (const float*)d_in[2];
    const float* b_out = (const float*)d_in[3];
    float* out = (float*)d_out;

    cudaFuncSetAttribute(mma_gemm_kernel,
                         cudaFuncAttributeMaxDynamicSharedMemorySize, G_SMEM);

    conv_split_kernel<<<MTOT, 256>>>(x);
    conv_w_kernel<<<dim3(32, 96), dim3(32, 32)>>>(w_qkv, 3072, 0);
    conv_w_kernel<<<dim3(32, 32), dim3(32, 32)>>>(w_out, 1024, 1);

    // GEMM1: qkv -> split q/k/v layouts
    mma_gemm_kernel<<<dim3(3072/128, MTOT/128), 256, G_SMEM>>>(nullptr, nullptr, 0);

    // attention (writes split GEMM2 input into g_Ax)
    attn_mma_kernel<<<dim3(SEQ/128, 64), 256>>>();

    // GEMM2: + bias -> out
    mma_gemm_kernel<<<dim3(DIMM/128, MTOT/128), 256, G_SMEM>>>(b_out, out, 1);
}

// round 13
// speedup vs baseline: 1.8041x; 1.8041x over previous
#include <cuda_runtime.h>
#include <cuda_bf16.h>
#include <cuda_fp16.h>
#include <stdint.h>

#define SEQ   2048
#define BATCH 4
#define NH    16
#define HD    64
#define DIMM  1024
#define GK    2048          // doubled K for fp16 2-term compensated GEMM
#define MTOT  8192
#define NKB   (GK/32)       // 64 k-blocks of 32

typedef __nv_bfloat16 bf16;

// ---------------- scratch (__device__ globals; referenced ONLY in device code)
__device__ bf16   g_q   [(size_t)64*SEQ*192];    // [bh][s][qh|ql|qh] bf16, pre-scaled
__device__ bf16   g_k   [(size_t)64*SEQ*192];    // [bh][s][kh|kh|kl] bf16
__device__ bf16   g_v   [(size_t)64*2*SEQ*64];   // [bh][plane hi/lo][s][d] bf16
__device__ __half g_Ax  [(size_t)MTOT*GK];       // fp16 [ah|al] activations
__device__ __half g_Bqkv[(size_t)3072*GK];       // fp16 [bh|bh] w_qkv^T
__device__ __half g_Bout[(size_t)1024*GK];       // fp16 [bh|bh] w_out^T

// ---------------- small helpers ---------------------------------------------
__device__ __forceinline__ uint32_t smem_u32(const void* p) {
    uint32_t a;
    asm("{ .reg .u64 t; cvta.to.shared.u64 t, %1; cvt.u32.u64 %0, t; }"
        : "=r"(a) : "l"(p));
    return a;
}
// bf16 pair pack: memory order [lo, hi]
__device__ __forceinline__ uint32_t pack2(float lo, float hi) {
    uint32_t r;
    asm("cvt.rn.bf16x2.f32 %0, %1, %2;" : "=r"(r) : "f"(hi), "f"(lo));
    return r;
}
__device__ __forceinline__ float lo_f(uint32_t x) { return __uint_as_float(x << 16); }
__device__ __forceinline__ float hi_f(uint32_t x) { return __uint_as_float(x & 0xffff0000u); }
// fp16 pair pack: memory order [lo, hi]
__device__ __forceinline__ uint32_t pack2h(float lo, float hi) {
    uint32_t r;
    asm("cvt.rn.f16x2.f32 %0, %1, %2;" : "=r"(r) : "f"(hi), "f"(lo));
    return r;
}
__device__ __forceinline__ float lo_h(uint32_t x) {
    return __half2float(__ushort_as_half((unsigned short)(x & 0xffffu)));
}
__device__ __forceinline__ float hi_h(uint32_t x) {
    return __half2float(__ushort_as_half((unsigned short)(x >> 16)));
}

__device__ __forceinline__ void ldsm_x4(uint32_t* r, uint32_t addr) {
    asm volatile("ldmatrix.sync.aligned.m8n8.x4.shared.b16 {%0,%1,%2,%3}, [%4];"
        : "=r"(r[0]), "=r"(r[1]), "=r"(r[2]), "=r"(r[3]) : "r"(addr));
}
__device__ __forceinline__ void ldsm_x4_t(uint32_t* r, uint32_t addr) {
    asm volatile("ldmatrix.sync.aligned.m8n8.x4.trans.shared.b16 {%0,%1,%2,%3}, [%4];"
        : "=r"(r[0]), "=r"(r[1]), "=r"(r[2]), "=r"(r[3]) : "r"(addr));
}
__device__ __forceinline__ void mma_bf16(float* d, const uint32_t* a, const uint32_t* b) {
    asm volatile(
        "mma.sync.aligned.m16n8k16.row.col.f32.bf16.bf16.f32 "
        "{%0,%1,%2,%3}, {%4,%5,%6,%7}, {%8,%9}, {%0,%1,%2,%3};"
        : "+f"(d[0]), "+f"(d[1]), "+f"(d[2]), "+f"(d[3])
        : "r"(a[0]), "r"(a[1]), "r"(a[2]), "r"(a[3]), "r"(b[0]), "r"(b[1]));
}
__device__ __forceinline__ void mma_f16(float* d, const uint32_t* a, const uint32_t* b) {
    asm volatile(
        "mma.sync.aligned.m16n8k16.row.col.f32.f16.f16.f32 "
        "{%0,%1,%2,%3}, {%4,%5,%6,%7}, {%8,%9}, {%0,%1,%2,%3};"
        : "+f"(d[0]), "+f"(d[1]), "+f"(d[2]), "+f"(d[3])
        : "r"(a[0]), "r"(a[1]), "r"(a[2]), "r"(a[3]), "r"(b[0]), "r"(b[1]));
}
__device__ __forceinline__ void cp16(uint32_t s, const void* g) {
    asm volatile("cp.async.cg.shared.global [%0], [%1], 16;" :: "r"(s), "l"(g));
}
#define CP_COMMIT()  asm volatile("cp.async.commit_group;" ::: "memory")
#define CP_WAIT1()   asm volatile("cp.async.wait_group 1;" ::: "memory")
#define CP_WAIT0()   asm volatile("cp.async.wait_group 0;" ::: "memory")

__device__ __forceinline__ void split_bf16(float v, bf16& hi, bf16& lo) {
    hi = __float2bfloat16(v);
    lo = __float2bfloat16(v - __bfloat162float(hi));
}
__device__ __forceinline__ void split_f16(float v, __half& hi, __half& lo) {
    hi = __float2half_rn(v);
    lo = __float2half_rn(v - __half2float(hi));
}

// ---------------- conversion kernels ----------------------------------------
// x[m][0:1024] f32 -> g_Ax[m][0:2048] fp16 = [hi | lo]
__global__ __launch_bounds__(256) void conv_split_kernel(const float* __restrict__ in)
{
    int idx = blockIdx.x * 256 + threadIdx.x;
    int m  = idx >> 8;
    int c4 = (idx & 255) << 2;
    float4 v = *(const float4*)(in + (size_t)m * DIMM + c4);
    __half h[4], l[4];
    split_f16(v.x, h[0], l[0]); split_f16(v.y, h[1], l[1]);
    split_f16(v.z, h[2], l[2]); split_f16(v.w, h[3], l[3]);
    size_t ro = (size_t)m * GK + c4;
    *(uint2*)(g_Ax + ro)        = *(uint2*)h;
    *(uint2*)(g_Ax + ro + 1024) = *(uint2*)l;
}

// w[k][n] f32 -> B'[n][0:2048] fp16 = [hi | hi]  (transpose)
__global__ void conv_w_kernel(const float* __restrict__ w, int N, int which)
{
    __shared__ float tile[32][33];
    __half* outB = which ? g_Bout : g_Bqkv;
    int tx = threadIdx.x, ty = threadIdx.y;
    int k0 = blockIdx.x * 32, n0 = blockIdx.y * 32;
    tile[ty][tx] = w[(size_t)(k0 + ty) * N + n0 + tx];
    __syncthreads();
    float v = tile[tx][ty];
    int n = n0 + ty, k = k0 + tx;
    __half hi = __float2half_rn(v);
    size_t ro = (size_t)n * GK + k;
    outB[ro]        = hi;
    outB[ro + 1024] = hi;
}

// ---------------- mma.sync GEMM (fp16 2-term): 128x128, warp 64x32, BK=32 ----
#define A_STG  10240                       // 128 x 40 fp16
#define G_SMEM (6 * A_STG)                 // 3 A stages + 3 B stages

__global__ __launch_bounds__(256, 1) void mma_gemm_kernel(const float* __restrict__ bias,
                                                          float* __restrict__ Cout,
                                                          int mode)
{
    extern __shared__ __align__(16) char gsm[];
    const uint32_t aBase = smem_u32(gsm);
    const uint32_t bBase = aBase + 3 * A_STG;
    const uint32_t aS[3] = { aBase, aBase + A_STG, aBase + 2*A_STG };
    const uint32_t bS[3] = { bBase, bBase + A_STG, bBase + 2*A_STG };

    const __half* A = g_Ax;
    const __half* B = mode ? g_Bout : g_Bqkv;

    const int t    = threadIdx.x;
    const int wid  = t >> 5;
    const int lane = t & 31;
    const int warp_m = wid & 1;
    const int warp_n = wid >> 1;
    const int n0 = blockIdx.x * 128;
    const int m0 = blockIdx.y * 128;

    const int lrow = t >> 1;
    const int lseg = (t & 1) * 16;
    const __half* Ap = A + (size_t)(m0 + lrow) * GK + lseg;
    const __half* Bp = B + (size_t)(n0 + lrow) * GK + lseg;
    const uint32_t sOff = (uint32_t)(lrow * 40 + lseg) * 2;

    const uint32_t aLd = (uint32_t)(((warp_m*64 + (lane & 15)) * 40) + (lane >> 4) * 8) * 2;
    const uint32_t bLd = (uint32_t)(((warp_n*32 + (lane >> 4)*8 + (lane & 7)) * 40)
                                    + ((lane >> 3) & 1) * 8) * 2;

    float acc[4][4][4];
#pragma unroll
    for (int i = 0; i < 4; i++)
#pragma unroll
        for (int j = 0; j < 4; j++)
#pragma unroll
            for (int q = 0; q < 4; q++) acc[i][j][q] = 0.0f;

    uint32_t afr[2][4][4];
    uint32_t bfr[2][4][2];

    auto load_frags = [&](int buf, uint32_t ab, uint32_t bb, int k0) {
#pragma unroll
        for (int mt = 0; mt < 4; mt++)
            ldsm_x4(afr[buf][mt], ab + aLd + (uint32_t)(mt*16*40 + k0) * 2);
#pragma unroll
        for (int ntp = 0; ntp < 4; ntp += 2) {
            uint32_t tmp[4];
            ldsm_x4(tmp, bb + bLd + (uint32_t)(ntp*8*40 + k0) * 2);
            bfr[buf][ntp][0] = tmp[0];   bfr[buf][ntp][1] = tmp[1];
            bfr[buf][ntp+1][0] = tmp[2]; bfr[buf][ntp+1][1] = tmp[3];
        }
    };
    auto hmma_block = [&](int buf) {
#pragma unroll
        for (int mt = 0; mt < 4; mt++)
#pragma unroll
            for (int nt = 0; nt < 4; nt++)
                mma_f16(acc[mt][nt], afr[buf][mt], bfr[buf][nt]);
    };
    auto issue_cp = [&](int kb, int s) {
        const __half* Ak = Ap + kb * 32;
        const __half* Bk = Bp + kb * 32;
        cp16(aS[s] + sOff, Ak);  cp16(aS[s] + sOff + 16, Ak + 8);
        cp16(bS[s] + sOff, Bk);  cp16(bS[s] + sOff + 16, Bk + 8);
        CP_COMMIT();
    };

    // prologue: stages 0,1 <- k-blocks 0,1
    issue_cp(0, 0);
    issue_cp(1, 1);
    CP_WAIT1();
    __syncthreads();
    load_frags(0, aS[0], bS[0], 0);

#define GSTEP(KB, S0, S1, S2) do {                                          \
        load_frags(1, aS[S0], bS[S0], 16);                                  \
        hmma_block(0);                                                      \
        if ((KB) + 2 < NKB) issue_cp((KB) + 2, (S2));                       \
        hmma_block(1);                                                      \
        if ((KB) + 1 < NKB) {                                               \
            if ((KB) + 2 < NKB) CP_WAIT1(); else CP_WAIT0();                \
            __syncthreads();                                                \
            load_frags(0, aS[S1], bS[S1], 0);                               \
        }                                                                   \
    } while (0)

    // NKB = 64 = 3*21 + 1: 21 unrolled triples + tail (63%3==0 -> stages 0,1,2)
    for (int kb3 = 0; kb3 < 63; kb3 += 3) {
        GSTEP(kb3 + 0, 0, 1, 2);
        GSTEP(kb3 + 1, 1, 2, 0);
        GSTEP(kb3 + 2, 2, 0, 1);
    }
    GSTEP(63, 0, 1, 2);
#undef GSTEP

    // ---------------- epilogue ----------------
#pragma unroll
    for (int mt = 0; mt < 4; mt++) {
#pragma unroll
        for (int nt = 0; nt < 4; nt++) {
            int m_lo = m0 + warp_m*64 + mt*16 + (lane >> 2);
            int n    = n0 + warp_n*32 + nt*8 + 2*(lane & 3);
#pragma unroll
            for (int half = 0; half < 2; half++) {
                int m = m_lo + half * 8;
                float v0 = acc[mt][nt][half*2 + 0];
                float v1 = acc[mt][nt][half*2 + 1];
                if (mode == 1) {
                    float2 bi = *(const float2*)&bias[n];
                    *(float2*)&Cout[(size_t)m * DIMM + n] =
                        make_float2(v0 + bi.x, v1 + bi.y);
                } else {
                    int part = n >> 10, h = (n >> 6) & 15, d = n & 63;
                    int b = m >> 11, s = m & 2047;
                    int bh = b * NH + h;
                    if (part == 0) { v0 *= 0.125f; v1 *= 0.125f; }
                    uint32_t h2 = pack2(v0, v1);
                    uint32_t l2 = pack2(v0 - lo_f(h2), v1 - hi_f(h2));
                    if (part == 0) {          // Q: [hi | lo | hi] bf16, pre-scaled
                        size_t base = ((size_t)bh * SEQ + s) * 192 + d;
                        *(uint32_t*)&g_q[base]       = h2;
                        *(uint32_t*)&g_q[base + 64]  = l2;
                        *(uint32_t*)&g_q[base + 128] = h2;
                    } else if (part == 1) {   // K: [hi | hi | lo] bf16
                        size_t base = ((size_t)bh * SEQ + s) * 192 + d;
                        *(uint32_t*)&g_k[base]       = h2;
                        *(uint32_t*)&g_k[base + 64]  = h2;
                        *(uint32_t*)&g_k[base + 128] = l2;
                    } else {                  // V: planes hi / lo bf16
                        size_t base = (((size_t)bh * 2) * SEQ + s) * 64 + d;
                        *(uint32_t*)&g_v[base]                 = h2;
                        *(uint32_t*)&g_v[base + (size_t)SEQ*64] = l2;
                    }
                }
            }
        }
    }
}

// ---------------- flash attention with mma.sync (R11 version, bf16 3-term) ---
__global__ __launch_bounds__(256) void attn_mma_kernel()
{
    __shared__ __align__(16) bf16 Ks[64][200];
    __shared__ __align__(16) bf16 Vh[64][72];
    __shared__ __align__(16) bf16 Vl[64][72];

    const int t    = threadIdx.x;
    const int wid  = t >> 5;
    const int lane = t & 31;
    const int bh   = blockIdx.y;
    const int q0   = blockIdx.x * 128;

    const bf16* Qg = g_q + (size_t)bh * SEQ * 192;
    const bf16* Kg = g_k + (size_t)bh * SEQ * 192;
    const bf16* Vg = g_v + (size_t)bh * 2 * SEQ * 64;

    const uint32_t ksBase = smem_u32(&Ks[0][0]);
    const uint32_t vhBase = smem_u32(&Vh[0][0]);
    const uint32_t vlBase = smem_u32(&Vl[0][0]);

    // ---- Q A-fragments directly from gmem (one-time) ----
    uint32_t qfr[12][4];
    {
        const bf16* Qr = Qg + (size_t)(q0 + 16*wid + (lane >> 2)) * 192 + (lane & 3) * 2;
#pragma unroll
        for (int ks = 0; ks < 12; ks++) {
            qfr[ks][0] = *(const uint32_t*)(Qr + ks*16);
            qfr[ks][1] = *(const uint32_t*)(Qr + 8*192 + ks*16);
            qfr[ks][2] = *(const uint32_t*)(Qr + ks*16 + 8);
            qfr[ks][3] = *(const uint32_t*)(Qr + 8*192 + ks*16 + 8);
        }
    }

    float acc_o[8][4];
#pragma unroll
    for (int i = 0; i < 8; i++)
#pragma unroll
        for (int j = 0; j < 4; j++) acc_o[i][j] = 0.0f;
    float m_lo = -1e30f, m_hi = -1e30f, l_lo = 0.0f, l_hi = 0.0f;

    for (int j0 = 0; j0 < SEQ; j0 += 64) {
        __syncthreads();                  // previous tile fully consumed
#pragma unroll
        for (int i = 0; i < 6; i++) {
            int idx = t + i * 256;        // 1536 8-elem chunks
            int r = idx / 24, c = idx % 24;
            *(uint4*)&Ks[r][c*8] =
                *(const uint4*)(Kg + (size_t)(j0 + r) * 192 + c*8);
        }
#pragma unroll
        for (int i = 0; i < 2; i++) {
            int idx = t + i * 256;        // 512
            int r = idx / 8, c = idx % 8;
            *(uint4*)&Vh[r][c*8] =
                *(const uint4*)(Vg + (size_t)(j0 + r) * 64 + c*8);
            *(uint4*)&Vl[r][c*8] =
                *(const uint4*)(Vg + (size_t)SEQ*64 + (size_t)(j0 + r) * 64 + c*8);
        }
        __syncthreads();

        // ---- S = Q' @ K'^T  (d'=192 contraction) ----
        float sc[8][4];
#pragma unroll
        for (int i = 0; i < 8; i++)
#pragma unroll
            for (int j = 0; j < 4; j++) sc[i][j] = 0.0f;

#pragma unroll
        for (int ks = 0; ks < 12; ks++) {
            const int k0 = ks * 16;
#pragma unroll
            for (int ntp = 0; ntp < 8; ntp += 2) {
                uint32_t tmp[4];
                ldsm_x4(tmp, ksBase +
                    (((ntp*8 + (lane >> 4)*8 + (lane & 7)) * 200)
                     + k0 + ((lane >> 3) & 1) * 8) * 2);
                mma_bf16(sc[ntp],   qfr[ks], tmp);
                mma_bf16(sc[ntp+1], qfr[ks], tmp + 2);
            }
        }

        // ---- online softmax (rows: lane>>2 and +8) ----
        float mx0 = -1e30f, mx1 = -1e30f;
#pragma unroll
        for (int nt = 0; nt < 8; nt++) {
            mx0 = fmaxf(mx0, fmaxf(sc[nt][0], sc[nt][1]));
            mx1 = fmaxf(mx1, fmaxf(sc[nt][2], sc[nt][3]));
        }
        mx0 = fmaxf(mx0, __shfl_xor_sync(0xffffffffu, mx0, 1));
        mx0 = fmaxf(mx0, __shfl_xor_sync(0xffffffffu, mx0, 2));
        mx1 = fmaxf(mx1, __shfl_xor_sync(0xffffffffu, mx1, 1));
        mx1 = fmaxf(mx1, __shfl_xor_sync(0xffffffffu, mx1, 2));
        float mn0 = fmaxf(m_lo, mx0), mn1 = fmaxf(m_hi, mx1);
        float f0 = __expf(m_lo - mn0), f1 = __expf(m_hi - mn1);
        m_lo = mn0; m_hi = mn1;

        float s0 = 0.0f, s1 = 0.0f;
#pragma unroll
        for (int nt = 0; nt < 8; nt++) {
            sc[nt][0] = __expf(sc[nt][0] - mn0); s0 += sc[nt][0];
            sc[nt][1] = __expf(sc[nt][1] - mn0); s0 += sc[nt][1];
            sc[nt][2] = __expf(sc[nt][2] - mn1); s1 += sc[nt][2];
            sc[nt][3] = __expf(sc[nt][3] - mn1); s1 += sc[nt][3];
        }
        s0 += __shfl_xor_sync(0xffffffffu, s0, 1);
        s0 += __shfl_xor_sync(0xffffffffu, s0, 2);
        s1 += __shfl_xor_sync(0xffffffffu, s1, 1);
        s1 += __shfl_xor_sync(0xffffffffu, s1, 2);
        l_lo = l_lo * f0 + s0;
        l_hi = l_hi * f1 + s1;
#pragma unroll
        for (int nt = 0; nt < 8; nt++) {
            acc_o[nt][0] *= f0; acc_o[nt][1] *= f0;
            acc_o[nt][2] *= f1; acc_o[nt][3] *= f1;
        }

        // ---- P fragments (C-layout == A-frag layout) ----
        uint32_t aph[4][4], apl[4][4];
#pragma unroll
        for (int kt = 0; kt < 4; kt++) {
            aph[kt][0] = pack2(sc[2*kt][0],   sc[2*kt][1]);
            aph[kt][1] = pack2(sc[2*kt][2],   sc[2*kt][3]);
            aph[kt][2] = pack2(sc[2*kt+1][0], sc[2*kt+1][1]);
            aph[kt][3] = pack2(sc[2*kt+1][2], sc[2*kt+1][3]);
            apl[kt][0] = pack2(sc[2*kt][0]   - lo_f(aph[kt][0]), sc[2*kt][1]   - hi_f(aph[kt][0]));
            apl[kt][1] = pack2(sc[2*kt][2]   - lo_f(aph[kt][1]), sc[2*kt][3]   - hi_f(aph[kt][1]));
            apl[kt][2] = pack2(sc[2*kt+1][0] - lo_f(aph[kt][2]), sc[2*kt+1][1] - hi_f(aph[kt][2]));
            apl[kt][3] = pack2(sc[2*kt+1][2] - lo_f(aph[kt][3]), sc[2*kt+1][3] - hi_f(aph[kt][3]));
        }

        // ---- O += P @ V  (ph*vh + pl*vh + ph*vl) ----
#pragma unroll
        for (int kt = 0; kt < 4; kt++) {
#pragma unroll
            for (int ntp = 0; ntp < 8; ntp += 2) {
                uint32_t bh4[4], bl4[4];
                uint32_t voff = (((kt*16 + (lane & 15)) * 72)
                                 + ntp*8 + (lane >> 4) * 8) * 2;
                ldsm_x4_t(bh4, vhBase + voff);
                ldsm_x4_t(bl4, vlBase + voff);
                mma_bf16(acc_o[ntp],   aph[kt], bh4);
                mma_bf16(acc_o[ntp],   apl[kt], bh4);
                mma_bf16(acc_o[ntp],   aph[kt], bl4);
                mma_bf16(acc_o[ntp+1], aph[kt], bh4 + 2);
                mma_bf16(acc_o[ntp+1], apl[kt], bh4 + 2);
                mma_bf16(acc_o[ntp+1], aph[kt], bl4 + 2);
            }
        }
    }

    // ---- finalize: reference reshape semantics (flat view of [B,H,S,D]):
    //   (b,h,s,d) -> row b*2048 + h*128 + (s>>4), col (s&15)*64 + d
    //   Emit fp16 [hi | lo] GEMM2 operand.
    float inv0 = 1.0f / l_lo, inv1 = 1.0f / l_hi;
    const int b = bh >> 4, h = bh & 15;
    const int s_base = q0 + 16*wid + (lane >> 2);
#pragma unroll
    for (int nt = 0; nt < 8; nt++) {
        int d = nt*8 + 2*(lane & 3);
#pragma unroll
        for (int half = 0; half < 2; half++) {
            int s = s_base + half * 8;
            int m   = b * 2048 + h * 128 + (s >> 4);
            int col = (s & 15) * 64 + d;
            float v0 = acc_o[nt][half*2 + 0] * (half ? inv1 : inv0);
            float v1 = acc_o[nt][half*2 + 1] * (half ? inv1 : inv0);
            uint32_t h2 = pack2h(v0, v1);
            uint32_t l2 = pack2h(v0 - lo_h(h2), v1 - hi_h(h2));
            size_t base = (size_t)m * GK + col;
            *(uint32_t*)&g_Ax[base]        = h2;
            *(uint32_t*)&g_Ax[base + 1024] = l2;
        }
    }
}

// ---------------------------------------------------------------------------
extern "C" void kernel_launch(void* const* d_in, const int* in_sizes, int n_in,
                              void* d_out, int out_size)
{
    const float* x     = (const float*)d_in[0];
    const float* w_qkv = (const float*)d_in[1];
    const float* w_out = (const float*)d_in[2];
    const float* b_out = (const float*)d_in[3];
    float* out = (float*)d_out;

    cudaFuncSetAttribute(mma_gemm_kernel,
                         cudaFuncAttributeMaxDynamicSharedMemorySize, G_SMEM);

    conv_split_kernel<<<MTOT, 256>>>(x);
    conv_w_kernel<<<dim3(32, 96), dim3(32, 32)>>>(w_qkv, 3072, 0);
    conv_w_kernel<<<dim3(32, 32), dim3(32, 32)>>>(w_out, 1024, 1);

    // GEMM1: qkv -> split q/k/v layouts
    mma_gemm_kernel<<<dim3(3072/128, MTOT/128), 256, G_SMEM>>>(nullptr, nullptr, 0);

    // attention (writes fp16 GEMM2 input into g_Ax)
    attn_mma_kernel<<<dim3(SEQ/128, 64), 256>>>();

    // GEMM2: + bias -> out
    mma_gemm_kernel<<<dim3(DIMM/128, MTOT/128), 256, G_SMEM>>>(b_out, out, 1);
}

// round 14
// speedup vs baseline: 2.0990x; 1.1635x over previous
#include <cuda_runtime.h>
#include <cuda_bf16.h>
#include <cuda_fp16.h>
#include <stdint.h>

#define SEQ   2048
#define BATCH 4
#define NH    16
#define HD    64
#define DIMM  1024
#define GK    2048          // doubled K for fp16 2-term compensated GEMM
#define MTOT  8192
#define NKB   (GK/32)       // 64 k-blocks of 32

typedef __nv_bfloat16 bf16;

// ---------------- scratch (__device__ globals; referenced ONLY in device code)
__device__ __half g_q   [(size_t)64*SEQ*128];    // [bh][s][qh|ql] fp16, pre-scaled
__device__ __half g_k   [(size_t)64*SEQ*128];    // [bh][s][kh|kh] fp16
__device__ __half g_v   [(size_t)64*SEQ*64];     // [bh][s][vh] fp16
__device__ __half g_Ax  [(size_t)MTOT*GK];       // fp16 [ah|al] activations
__device__ __half g_Bqkv[(size_t)3072*GK];       // fp16 [bh|bh] w_qkv^T
__device__ __half g_Bout[(size_t)1024*GK];       // fp16 [bh|bh] w_out^T

// ---------------- small helpers ---------------------------------------------
__device__ __forceinline__ uint32_t smem_u32(const void* p) {
    uint32_t a;
    asm("{ .reg .u64 t; cvta.to.shared.u64 t, %1; cvt.u32.u64 %0, t; }"
        : "=r"(a) : "l"(p));
    return a;
}
// fp16 pair pack: memory order [lo, hi]
__device__ __forceinline__ uint32_t pack2h(float lo, float hi) {
    uint32_t r;
    asm("cvt.rn.f16x2.f32 %0, %1, %2;" : "=r"(r) : "f"(hi), "f"(lo));
    return r;
}
__device__ __forceinline__ float lo_h(uint32_t x) {
    return __half2float(__ushort_as_half((unsigned short)(x & 0xffffu)));
}
__device__ __forceinline__ float hi_h(uint32_t x) {
    return __half2float(__ushort_as_half((unsigned short)(x >> 16)));
}

__device__ __forceinline__ void ldsm_x4(uint32_t* r, uint32_t addr) {
    asm volatile("ldmatrix.sync.aligned.m8n8.x4.shared.b16 {%0,%1,%2,%3}, [%4];"
        : "=r"(r[0]), "=r"(r[1]), "=r"(r[2]), "=r"(r[3]) : "r"(addr));
}
__device__ __forceinline__ void ldsm_x4_t(uint32_t* r, uint32_t addr) {
    asm volatile("ldmatrix.sync.aligned.m8n8.x4.trans.shared.b16 {%0,%1,%2,%3}, [%4];"
        : "=r"(r[0]), "=r"(r[1]), "=r"(r[2]), "=r"(r[3]) : "r"(addr));
}
__device__ __forceinline__ void mma_f16(float* d, const uint32_t* a, const uint32_t* b) {
    asm volatile(
        "mma.sync.aligned.m16n8k16.row.col.f32.f16.f16.f32 "
        "{%0,%1,%2,%3}, {%4,%5,%6,%7}, {%8,%9}, {%0,%1,%2,%3};"
        : "+f"(d[0]), "+f"(d[1]), "+f"(d[2]), "+f"(d[3])
        : "r"(a[0]), "r"(a[1]), "r"(a[2]), "r"(a[3]), "r"(b[0]), "r"(b[1]));
}
__device__ __forceinline__ void cp16(uint32_t s, const void* g) {
    asm volatile("cp.async.cg.shared.global [%0], [%1], 16;" :: "r"(s), "l"(g));
}
#define CP_COMMIT()  asm volatile("cp.async.commit_group;" ::: "memory")
#define CP_WAIT1()   asm volatile("cp.async.wait_group 1;" ::: "memory")
#define CP_WAIT0()   asm volatile("cp.async.wait_group 0;" ::: "memory")

__device__ __forceinline__ void split_f16(float v, __half& hi, __half& lo) {
    hi = __float2half_rn(v);
    lo = __float2half_rn(v - __half2float(hi));
}

// ---------------- conversion kernels ----------------------------------------
// x[m][0:1024] f32 -> g_Ax[m][0:2048] fp16 = [hi | lo]
__global__ __launch_bounds__(256) void conv_split_kernel(const float* __restrict__ in)
{
    int idx = blockIdx.x * 256 + threadIdx.x;
    int m  = idx >> 8;
    int c4 = (idx & 255) << 2;
    float4 v = *(const float4*)(in + (size_t)m * DIMM + c4);
    __half h[4], l[4];
    split_f16(v.x, h[0], l[0]); split_f16(v.y, h[1], l[1]);
    split_f16(v.z, h[2], l[2]); split_f16(v.w, h[3], l[3]);
    size_t ro = (size_t)m * GK + c4;
    *(uint2*)(g_Ax + ro)        = *(uint2*)h;
    *(uint2*)(g_Ax + ro + 1024) = *(uint2*)l;
}

// w[k][n] f32 -> B'[n][0:2048] fp16 = [hi | hi]  (transpose)
__global__ void conv_w_kernel(const float* __restrict__ w, int N, int which)
{
    __shared__ float tile[32][33];
    __half* outB = which ? g_Bout : g_Bqkv;
    int tx = threadIdx.x, ty = threadIdx.y;
    int k0 = blockIdx.x * 32, n0 = blockIdx.y * 32;
    tile[ty][tx] = w[(size_t)(k0 + ty) * N + n0 + tx];
    __syncthreads();
    float v = tile[tx][ty];
    int n = n0 + ty, k = k0 + tx;
    __half hi = __float2half_rn(v);
    size_t ro = (size_t)n * GK + k;
    outB[ro]        = hi;
    outB[ro + 1024] = hi;
}

// ---------------- mma.sync GEMM (fp16 2-term): 128x128, warp 64x32, BK=32 ----
#define A_STG  10240                       // 128 x 40 fp16
#define G_SMEM (6 * A_STG)                 // 3 A stages + 3 B stages

__global__ __launch_bounds__(256, 1) void mma_gemm_kernel(const float* __restrict__ bias,
                                                          float* __restrict__ Cout,
                                                          int mode)
{
    extern __shared__ __align__(16) char gsm[];
    const uint32_t aBase = smem_u32(gsm);
    const uint32_t bBase = aBase + 3 * A_STG;
    const uint32_t aS[3] = { aBase, aBase + A_STG, aBase + 2*A_STG };
    const uint32_t bS[3] = { bBase, bBase + A_STG, bBase + 2*A_STG };

    const __half* A = g_Ax;
    const __half* B = mode ? g_Bout : g_Bqkv;

    const int t    = threadIdx.x;
    const int wid  = t >> 5;
    const int lane = t & 31;
    const int warp_m = wid & 1;
    const int warp_n = wid >> 1;
    const int n0 = blockIdx.x * 128;
    const int m0 = blockIdx.y * 128;

    const int lrow = t >> 1;
    const int lseg = (t & 1) * 16;
    const __half* Ap = A + (size_t)(m0 + lrow) * GK + lseg;
    const __half* Bp = B + (size_t)(n0 + lrow) * GK + lseg;
    const uint32_t sOff = (uint32_t)(lrow * 40 + lseg) * 2;

    const uint32_t aLd = (uint32_t)(((warp_m*64 + (lane & 15)) * 40) + (lane >> 4) * 8) * 2;
    const uint32_t bLd = (uint32_t)(((warp_n*32 + (lane >> 4)*8 + (lane & 7)) * 40)
                                    + ((lane >> 3) & 1) * 8) * 2;

    float acc[4][4][4];
#pragma unroll
    for (int i = 0; i < 4; i++)
#pragma unroll
        for (int j = 0; j < 4; j++)
#pragma unroll
            for (int q = 0; q < 4; q++) acc[i][j][q] = 0.0f;

    uint32_t afr[2][4][4];
    uint32_t bfr[2][4][2];

    auto load_frags = [&](int buf, uint32_t ab, uint32_t bb, int k0) {
#pragma unroll
        for (int mt = 0; mt < 4; mt++)
            ldsm_x4(afr[buf][mt], ab + aLd + (uint32_t)(mt*16*40 + k0) * 2);
#pragma unroll
        for (int ntp = 0; ntp < 4; ntp += 2) {
            uint32_t tmp[4];
            ldsm_x4(tmp, bb + bLd + (uint32_t)(ntp*8*40 + k0) * 2);
            bfr[buf][ntp][0] = tmp[0];   bfr[buf][ntp][1] = tmp[1];
            bfr[buf][ntp+1][0] = tmp[2]; bfr[buf][ntp+1][1] = tmp[3];
        }
    };
    auto hmma_block = [&](int buf) {
#pragma unroll
        for (int mt = 0; mt < 4; mt++)
#pragma unroll
            for (int nt = 0; nt < 4; nt++)
                mma_f16(acc[mt][nt], afr[buf][mt], bfr[buf][nt]);
    };
    auto issue_cp = [&](int kb, int s) {
        const __half* Ak = Ap + kb * 32;
        const __half* Bk = Bp + kb * 32;
        cp16(aS[s] + sOff, Ak);  cp16(aS[s] + sOff + 16, Ak + 8);
        cp16(bS[s] + sOff, Bk);  cp16(bS[s] + sOff + 16, Bk + 8);
        CP_COMMIT();
    };

    issue_cp(0, 0);
    issue_cp(1, 1);
    CP_WAIT1();
    __syncthreads();
    load_frags(0, aS[0], bS[0], 0);

#define GSTEP(KB, S0, S1, S2) do {                                          \
        load_frags(1, aS[S0], bS[S0], 16);                                  \
        hmma_block(0);                                                      \
        if ((KB) + 2 < NKB) issue_cp((KB) + 2, (S2));                       \
        hmma_block(1);                                                      \
        if ((KB) + 1 < NKB) {                                               \
            if ((KB) + 2 < NKB) CP_WAIT1(); else CP_WAIT0();                \
            __syncthreads();                                                \
            load_frags(0, aS[S1], bS[S1], 0);                               \
        }                                                                   \
    } while (0)

    // NKB = 64 = 3*21 + 1
    for (int kb3 = 0; kb3 < 63; kb3 += 3) {
        GSTEP(kb3 + 0, 0, 1, 2);
        GSTEP(kb3 + 1, 1, 2, 0);
        GSTEP(kb3 + 2, 2, 0, 1);
    }
    GSTEP(63, 0, 1, 2);
#undef GSTEP

    // ---------------- epilogue ----------------
#pragma unroll
    for (int mt = 0; mt < 4; mt++) {
#pragma unroll
        for (int nt = 0; nt < 4; nt++) {
            int m_lo = m0 + warp_m*64 + mt*16 + (lane >> 2);
            int n    = n0 + warp_n*32 + nt*8 + 2*(lane & 3);
#pragma unroll
            for (int half = 0; half < 2; half++) {
                int m = m_lo + half * 8;
                float v0 = acc[mt][nt][half*2 + 0];
                float v1 = acc[mt][nt][half*2 + 1];
                if (mode == 1) {
                    float2 bi = *(const float2*)&bias[n];
                    *(float2*)&Cout[(size_t)m * DIMM + n] =
                        make_float2(v0 + bi.x, v1 + bi.y);
                } else {
                    int part = n >> 10, h = (n >> 6) & 15, d = n & 63;
                    int b = m >> 11, s = m & 2047;
                    int bh = b * NH + h;
                    if (part == 0) {          // Q: [qh | ql] fp16, pre-scaled
                        v0 *= 0.125f; v1 *= 0.125f;
                        uint32_t h2 = pack2h(v0, v1);
                        uint32_t l2 = pack2h(v0 - lo_h(h2), v1 - hi_h(h2));
                        size_t base = ((size_t)bh * SEQ + s) * 128 + d;
                        *(uint32_t*)&g_q[base]      = h2;
                        *(uint32_t*)&g_q[base + 64] = l2;
                    } else if (part == 1) {   // K: [kh | kh] fp16
                        uint32_t h2 = pack2h(v0, v1);
                        size_t base = ((size_t)bh * SEQ + s) * 128 + d;
                        *(uint32_t*)&g_k[base]      = h2;
                        *(uint32_t*)&g_k[base + 64] = h2;
                    } else {                  // V: single fp16 plane
                        uint32_t h2 = pack2h(v0, v1);
                        size_t base = ((size_t)bh * SEQ + s) * 64 + d;
                        *(uint32_t*)&g_v[base] = h2;
                    }
                }
            }
        }
    }
}

// ---------------- flash attention, fp16 2-term (d'=128, single V plane) ------
__global__ __launch_bounds__(256) void attn_mma_kernel()
{
    __shared__ __align__(16) __half Ks[64][136];
    __shared__ __align__(16) __half Vs[64][72];

    const int t    = threadIdx.x;
    const int wid  = t >> 5;
    const int lane = t & 31;
    const int bh   = blockIdx.y;
    const int q0   = blockIdx.x * 128;

    const __half* Qg = g_q + (size_t)bh * SEQ * 128;
    const __half* Kg = g_k + (size_t)bh * SEQ * 128;
    const __half* Vg = g_v + (size_t)bh * SEQ * 64;

    const uint32_t ksBase = smem_u32(&Ks[0][0]);
    const uint32_t vsBase = smem_u32(&Vs[0][0]);

    // ---- Q A-fragments directly from gmem (one-time; 8 k-steps) ----
    uint32_t qfr[8][4];
    {
        const __half* Qr = Qg + (size_t)(q0 + 16*wid + (lane >> 2)) * 128 + (lane & 3) * 2;
#pragma unroll
        for (int ks = 0; ks < 8; ks++) {
            qfr[ks][0] = *(const uint32_t*)(Qr + ks*16);
            qfr[ks][1] = *(const uint32_t*)(Qr + 8*128 + ks*16);
            qfr[ks][2] = *(const uint32_t*)(Qr + ks*16 + 8);
            qfr[ks][3] = *(const uint32_t*)(Qr + 8*128 + ks*16 + 8);
        }
    }

    float acc_o[8][4];
#pragma unroll
    for (int i = 0; i < 8; i++)
#pragma unroll
        for (int j = 0; j < 4; j++) acc_o[i][j] = 0.0f;
    float m_lo = -1e30f, m_hi = -1e30f, l_lo = 0.0f, l_hi = 0.0f;

    for (int j0 = 0; j0 < SEQ; j0 += 64) {
        __syncthreads();                  // previous tile fully consumed
        // K' tile 64x128 fp16 (stride 136), V tile 64x64 fp16 (stride 72)
#pragma unroll
        for (int i = 0; i < 4; i++) {
            int idx = t + i * 256;        // 1024 chunks of 8 fp16
            int r = idx >> 4, c = idx & 15;
            *(uint4*)&Ks[r][c*8] =
                *(const uint4*)(Kg + (size_t)(j0 + r) * 128 + c*8);
        }
#pragma unroll
        for (int i = 0; i < 2; i++) {
            int idx = t + i * 256;        // 512 chunks
            int r = idx >> 3, c = idx & 7;
            *(uint4*)&Vs[r][c*8] =
                *(const uint4*)(Vg + (size_t)(j0 + r) * 64 + c*8);
        }
        __syncthreads();

        // ---- S = Q' @ K'^T  (d'=128, 8 k-steps) ----
        float sc[8][4];
#pragma unroll
        for (int i = 0; i < 8; i++)
#pragma unroll
            for (int j = 0; j < 4; j++) sc[i][j] = 0.0f;

#pragma unroll
        for (int ks = 0; ks < 8; ks++) {
            const int k0 = ks * 16;
#pragma unroll
            for (int ntp = 0; ntp < 8; ntp += 2) {
                uint32_t tmp[4];
                ldsm_x4(tmp, ksBase +
                    (((ntp*8 + (lane >> 4)*8 + (lane & 7)) * 136)
                     + k0 + ((lane >> 3) & 1) * 8) * 2);
                mma_f16(sc[ntp],   qfr[ks], tmp);
                mma_f16(sc[ntp+1], qfr[ks], tmp + 2);
            }
        }

        // ---- online softmax (rows: lane>>2 and +8) ----
        float mx0 = -1e30f, mx1 = -1e30f;
#pragma unroll
        for (int nt = 0; nt < 8; nt++) {
            mx0 = fmaxf(mx0, fmaxf(sc[nt][0], sc[nt][1]));
            mx1 = fmaxf(mx1, fmaxf(sc[nt][2], sc[nt][3]));
        }
        mx0 = fmaxf(mx0, __shfl_xor_sync(0xffffffffu, mx0, 1));
        mx0 = fmaxf(mx0, __shfl_xor_sync(0xffffffffu, mx0, 2));
        mx1 = fmaxf(mx1, __shfl_xor_sync(0xffffffffu, mx1, 1));
        mx1 = fmaxf(mx1, __shfl_xor_sync(0xffffffffu, mx1, 2));
        float mn0 = fmaxf(m_lo, mx0), mn1 = fmaxf(m_hi, mx1);
        float f0 = __expf(m_lo - mn0), f1 = __expf(m_hi - mn1);
        m_lo = mn0; m_hi = mn1;

        float s0 = 0.0f, s1 = 0.0f;
#pragma unroll
        for (int nt = 0; nt < 8; nt++) {
            sc[nt][0] = __expf(sc[nt][0] - mn0); s0 += sc[nt][0];
            sc[nt][1] = __expf(sc[nt][1] - mn0); s0 += sc[nt][1];
            sc[nt][2] = __expf(sc[nt][2] - mn1); s1 += sc[nt][2];
            sc[nt][3] = __expf(sc[nt][3] - mn1); s1 += sc[nt][3];
        }
        s0 += __shfl_xor_sync(0xffffffffu, s0, 1);
        s0 += __shfl_xor_sync(0xffffffffu, s0, 2);
        s1 += __shfl_xor_sync(0xffffffffu, s1, 1);
        s1 += __shfl_xor_sync(0xffffffffu, s1, 2);
        l_lo = l_lo * f0 + s0;
        l_hi = l_hi * f1 + s1;
#pragma unroll
        for (int nt = 0; nt < 8; nt++) {
            acc_o[nt][0] *= f0; acc_o[nt][1] *= f0;
            acc_o[nt][2] *= f1; acc_o[nt][3] *= f1;
        }

        // ---- P fragments in fp16 hi/lo (C-layout == A-frag layout) ----
        uint32_t aph[4][4], apl[4][4];
#pragma unroll
        for (int kt = 0; kt < 4; kt++) {
            aph[kt][0] = pack2h(sc[2*kt][0],   sc[2*kt][1]);
            aph[kt][1] = pack2h(sc[2*kt][2],   sc[2*kt][3]);
            aph[kt][2] = pack2h(sc[2*kt+1][0], sc[2*kt+1][1]);
            aph[kt][3] = pack2h(sc[2*kt+1][2], sc[2*kt+1][3]);
            apl[kt][0] = pack2h(sc[2*kt][0]   - lo_h(aph[kt][0]), sc[2*kt][1]   - hi_h(aph[kt][0]));
            apl[kt][1] = pack2h(sc[2*kt][2]   - lo_h(aph[kt][1]), sc[2*kt][3]   - hi_h(aph[kt][1]));
            apl[kt][2] = pack2h(sc[2*kt+1][0] - lo_h(aph[kt][2]), sc[2*kt+1][1] - hi_h(aph[kt][2]));
            apl[kt][3] = pack2h(sc[2*kt+1][2] - lo_h(aph[kt][3]), sc[2*kt+1][3] - hi_h(aph[kt][3]));
        }

        // ---- O += P @ V   ((ph+pl)·vh; single V plane) ----
#pragma unroll
        for (int kt = 0; kt < 4; kt++) {
#pragma unroll
            for (int ntp = 0; ntp < 8; ntp += 2) {
                uint32_t vh4[4];
                uint32_t voff = (((kt*16 + (lane & 15)) * 72)
                                 + ntp*8 + (lane >> 4) * 8) * 2;
                ldsm_x4_t(vh4, vsBase + voff);
                mma_f16(acc_o[ntp],   aph[kt], vh4);
                mma_f16(acc_o[ntp],   apl[kt], vh4);
                mma_f16(acc_o[ntp+1], aph[kt], vh4 + 2);
                mma_f16(acc_o[ntp+1], apl[kt], vh4 + 2);
            }
        }
    }

    // ---- finalize: reference reshape semantics (flat view of [B,H,S,D]):
    //   (b,h,s,d) -> row b*2048 + h*128 + (s>>4), col (s&15)*64 + d
    //   Emit fp16 [hi | lo] GEMM2 operand.
    float inv0 = 1.0f / l_lo, inv1 = 1.0f / l_hi;
    const int b = bh >> 4, h = bh & 15;
    const int s_base = q0 + 16*wid + (lane >> 2);
#pragma unroll
    for (int nt = 0; nt < 8; nt++) {
        int d = nt*8 + 2*(lane & 3);
#pragma unroll
        for (int half = 0; half < 2; half++) {
            int s = s_base + half * 8;
            int m   = b * 2048 + h * 128 + (s >> 4);
            int col = (s & 15) * 64 + d;
            float v0 = acc_o[nt][half*2 + 0] * (half ? inv1 : inv0);
            float v1 = acc_o[nt][half*2 + 1] * (half ? inv1 : inv0);
            uint32_t h2 = pack2h(v0, v1);
            uint32_t l2 = pack2h(v0 - lo_h(h2), v1 - hi_h(h2));
            size_t base = (size_t)m * GK + col;
            *(uint32_t*)&g_Ax[base]        = h2;
            *(uint32_t*)&g_Ax[base + 1024] = l2;
        }
    }
}

// ---------------------------------------------------------------------------
extern "C" void kernel_launch(void* const* d_in, const int* in_sizes, int n_in,
                              void* d_out, int out_size)
{
    const float* x     = (const float*)d_in[0];
    const float* w_qkv = (const float*)d_in[1];
    const float* w_out = (const float*)d_in[2];
    const float* b_out = (const float*)d_in[3];
    float* out = (float*)d_out;

    cudaFuncSetAttribute(mma_gemm_kernel,
                         cudaFuncAttributeMaxDynamicSharedMemorySize, G_SMEM);

    conv_split_kernel<<<MTOT, 256>>>(x);
    conv_w_kernel<<<dim3(32, 96), dim3(32, 32)>>>(w_qkv, 3072, 0);
    conv_w_kernel<<<dim3(32, 32), dim3(32, 32)>>>(w_out, 1024, 1);

    // GEMM1: qkv -> fp16 q/k/v layouts
    mma_gemm_kernel<<<dim3(3072/128, MTOT/128), 256, G_SMEM>>>(nullptr, nullptr, 0);

    // attention (writes fp16 GEMM2 input into g_Ax)
    attn_mma_kernel<<<dim3(SEQ/128, 64), 256>>>();

    // GEMM2: + bias -> out
    mma_gemm_kernel<<<dim3(DIMM/128, MTOT/128), 256, G_SMEM>>>(b_out, out, 1);
}

// round 15
// speedup vs baseline: 2.3822x; 1.1349x over previous
#include <cuda_runtime.h>
#include <cuda_bf16.h>
#include <cuda_fp16.h>
#include <stdint.h>

#define SEQ   2048
#define BATCH 4
#define NH    16
#define HD    64
#define DIMM  1024
#define GK    2048          // doubled K for fp16 2-term compensated GEMM
#define MTOT  8192

typedef __nv_bfloat16 bf16;

// ---------------- scratch (__device__ globals; referenced ONLY in device code)
__device__ __half g_q   [(size_t)64*SEQ*128];    // [bh][s][qh|ql] fp16, pre-scaled
__device__ __half g_k   [(size_t)64*SEQ*128];    // [bh][s][kh|kh] fp16
__device__ __half g_v   [(size_t)64*SEQ*64];     // [bh][s][vh] fp16
__device__ __half g_Ax  [(size_t)MTOT*GK];       // fp16 [ah|al] activations
__device__ __half g_Bqkv[(size_t)3072*GK];       // fp16 [bh|bh] w_qkv^T
__device__ __half g_Bout[(size_t)1024*GK];       // fp16 [bh|bh] w_out^T

// ---------------- small helpers ---------------------------------------------
__device__ __forceinline__ uint32_t smem_u32(const void* p) {
    uint32_t a;
    asm("{ .reg .u64 t; cvta.to.shared.u64 t, %1; cvt.u32.u64 %0, t; }"
        : "=r"(a) : "l"(p));
    return a;
}
// fp16 pair pack: memory order [lo, hi]
__device__ __forceinline__ uint32_t pack2h(float lo, float hi) {
    uint32_t r;
    asm("cvt.rn.f16x2.f32 %0, %1, %2;" : "=r"(r) : "f"(hi), "f"(lo));
    return r;
}
__device__ __forceinline__ float lo_h(uint32_t x) {
    return __half2float(__ushort_as_half((unsigned short)(x & 0xffffu)));
}
__device__ __forceinline__ float hi_h(uint32_t x) {
    return __half2float(__ushort_as_half((unsigned short)(x >> 16)));
}

__device__ __forceinline__ void ldsm_x4(uint32_t* r, uint32_t addr) {
    asm volatile("ldmatrix.sync.aligned.m8n8.x4.shared.b16 {%0,%1,%2,%3}, [%4];"
        : "=r"(r[0]), "=r"(r[1]), "=r"(r[2]), "=r"(r[3]) : "r"(addr));
}
__device__ __forceinline__ void ldsm_x4_t(uint32_t* r, uint32_t addr) {
    asm volatile("ldmatrix.sync.aligned.m8n8.x4.trans.shared.b16 {%0,%1,%2,%3}, [%4];"
        : "=r"(r[0]), "=r"(r[1]), "=r"(r[2]), "=r"(r[3]) : "r"(addr));
}
__device__ __forceinline__ void mma_f16(float* d, const uint32_t* a, const uint32_t* b) {
    asm volatile(
        "mma.sync.aligned.m16n8k16.row.col.f32.f16.f16.f32 "
        "{%0,%1,%2,%3}, {%4,%5,%6,%7}, {%8,%9}, {%0,%1,%2,%3};"
        : "+f"(d[0]), "+f"(d[1]), "+f"(d[2]), "+f"(d[3])
        : "r"(a[0]), "r"(a[1]), "r"(a[2]), "r"(a[3]), "r"(b[0]), "r"(b[1]));
}
__device__ __forceinline__ void cp16(uint32_t s, const void* g) {
    asm volatile("cp.async.cg.shared.global [%0], [%1], 16;" :: "r"(s), "l"(g));
}
#define CP_COMMIT()  asm volatile("cp.async.commit_group;" ::: "memory")
#define CP_WAIT1()   asm volatile("cp.async.wait_group 1;" ::: "memory")
#define CP_WAIT0()   asm volatile("cp.async.wait_group 0;" ::: "memory")

__device__ __forceinline__ void split_f16(float v, __half& hi, __half& lo) {
    hi = __float2half_rn(v);
    lo = __float2half_rn(v - __half2float(hi));
}

// ---------------- conversion kernels ----------------------------------------
// x[m][0:1024] f32 -> g_Ax[m][0:2048] fp16 = [hi | lo]
__global__ __launch_bounds__(256) void conv_split_kernel(const float* __restrict__ in)
{
    int idx = blockIdx.x * 256 + threadIdx.x;
    int m  = idx >> 8;
    int c4 = (idx & 255) << 2;
    float4 v = *(const float4*)(in + (size_t)m * DIMM + c4);
    __half h[4], l[4];
    split_f16(v.x, h[0], l[0]); split_f16(v.y, h[1], l[1]);
    split_f16(v.z, h[2], l[2]); split_f16(v.w, h[3], l[3]);
    size_t ro = (size_t)m * GK + c4;
    *(uint2*)(g_Ax + ro)        = *(uint2*)h;
    *(uint2*)(g_Ax + ro + 1024) = *(uint2*)l;
}

// w[k][n] f32 -> B'[n][0:2048] fp16 = [hi | hi]  (transpose)
__global__ void conv_w_kernel(const float* __restrict__ w, int N, int which)
{
    __shared__ float tile[32][33];
    __half* outB = which ? g_Bout : g_Bqkv;
    int tx = threadIdx.x, ty = threadIdx.y;
    int k0 = blockIdx.x * 32, n0 = blockIdx.y * 32;
    tile[ty][tx] = w[(size_t)(k0 + ty) * N + n0 + tx];
    __syncthreads();
    float v = tile[tx][ty];
    int n = n0 + ty, k = k0 + tx;
    __half hi = __float2half_rn(v);
    size_t ro = (size_t)n * GK + k;
    outB[ro]        = hi;
    outB[ro + 1024] = hi;
}

// ---------------- mma.sync GEMM (fp16): 128x128, warp 64x32, BK=32 -----------
// NKBT = 64: 2-term (full K'); NKBT = 32: 1-term (hi halves only).
#define A_STG  10240                       // 128 x 40 fp16
#define G_SMEM (6 * A_STG)                 // 3 A stages + 3 B stages

template<int NKBT>
__global__ __launch_bounds__(256, 1) void mma_gemm_kernel(const float* __restrict__ bias,
                                                          float* __restrict__ Cout,
                                                          int mode, int noff)
{
    extern __shared__ __align__(16) char gsm[];
    const uint32_t aBase = smem_u32(gsm);
    const uint32_t bBase = aBase + 3 * A_STG;
    const uint32_t aS[3] = { aBase, aBase + A_STG, aBase + 2*A_STG };
    const uint32_t bS[3] = { bBase, bBase + A_STG, bBase + 2*A_STG };

    const __half* A = g_Ax;
    const __half* B = mode ? g_Bout : g_Bqkv;

    const int t    = threadIdx.x;
    const int wid  = t >> 5;
    const int lane = t & 31;
    const int warp_m = wid & 1;
    const int warp_n = wid >> 1;
    const int n0 = blockIdx.x * 128 + noff;
    const int m0 = blockIdx.y * 128;

    const int lrow = t >> 1;
    const int lseg = (t & 1) * 16;
    const __half* Ap = A + (size_t)(m0 + lrow) * GK + lseg;
    const __half* Bp = B + (size_t)(n0 + lrow) * GK + lseg;
    const uint32_t sOff = (uint32_t)(lrow * 40 + lseg) * 2;

    const uint32_t aLd = (uint32_t)(((warp_m*64 + (lane & 15)) * 40) + (lane >> 4) * 8) * 2;
    const uint32_t bLd = (uint32_t)(((warp_n*32 + (lane >> 4)*8 + (lane & 7)) * 40)
                                    + ((lane >> 3) & 1) * 8) * 2;

    float acc[4][4][4];
#pragma unroll
    for (int i = 0; i < 4; i++)
#pragma unroll
        for (int j = 0; j < 4; j++)
#pragma unroll
            for (int q = 0; q < 4; q++) acc[i][j][q] = 0.0f;

    uint32_t afr[2][4][4];
    uint32_t bfr[2][4][2];

    auto load_frags = [&](int buf, uint32_t ab, uint32_t bb, int k0) {
#pragma unroll
        for (int mt = 0; mt < 4; mt++)
            ldsm_x4(afr[buf][mt], ab + aLd + (uint32_t)(mt*16*40 + k0) * 2);
#pragma unroll
        for (int ntp = 0; ntp < 4; ntp += 2) {
            uint32_t tmp[4];
            ldsm_x4(tmp, bb + bLd + (uint32_t)(ntp*8*40 + k0) * 2);
            bfr[buf][ntp][0] = tmp[0];   bfr[buf][ntp][1] = tmp[1];
            bfr[buf][ntp+1][0] = tmp[2]; bfr[buf][ntp+1][1] = tmp[3];
        }
    };
    auto hmma_block = [&](int buf) {
#pragma unroll
        for (int mt = 0; mt < 4; mt++)
#pragma unroll
            for (int nt = 0; nt < 4; nt++)
                mma_f16(acc[mt][nt], afr[buf][mt], bfr[buf][nt]);
    };
    auto issue_cp = [&](int kb, int s) {
        const __half* Ak = Ap + kb * 32;
        const __half* Bk = Bp + kb * 32;
        cp16(aS[s] + sOff, Ak);  cp16(aS[s] + sOff + 16, Ak + 8);
        cp16(bS[s] + sOff, Bk);  cp16(bS[s] + sOff + 16, Bk + 8);
        CP_COMMIT();
    };

    issue_cp(0, 0);
    issue_cp(1, 1);
    CP_WAIT1();
    __syncthreads();
    load_frags(0, aS[0], bS[0], 0);

#define GSTEP(KB, S0, S1, S2) do {                                          \
        load_frags(1, aS[S0], bS[S0], 16);                                  \
        hmma_block(0);                                                      \
        if ((KB) + 2 < NKBT) issue_cp((KB) + 2, (S2));                      \
        hmma_block(1);                                                      \
        if ((KB) + 1 < NKBT) {                                              \
            if ((KB) + 2 < NKBT) CP_WAIT1(); else CP_WAIT0();               \
            __syncthreads();                                                \
            load_frags(0, aS[S1], bS[S1], 0);                               \
        }                                                                   \
    } while (0)

    constexpr int T3 = (NKBT / 3) * 3;     // full triples
    for (int kb3 = 0; kb3 < T3; kb3 += 3) {
        GSTEP(kb3 + 0, 0, 1, 2);
        GSTEP(kb3 + 1, 1, 2, 0);
        GSTEP(kb3 + 2, 2, 0, 1);
    }
    if (NKBT % 3 >= 1) GSTEP(T3,     0, 1, 2);
    if (NKBT % 3 >= 2) GSTEP(T3 + 1, 1, 2, 0);
#undef GSTEP

    // ---------------- epilogue ----------------
#pragma unroll
    for (int mt = 0; mt < 4; mt++) {
#pragma unroll
        for (int nt = 0; nt < 4; nt++) {
            int m_lo = m0 + warp_m*64 + mt*16 + (lane >> 2);
            int n    = n0 + warp_n*32 + nt*8 + 2*(lane & 3);
#pragma unroll
            for (int half = 0; half < 2; half++) {
                int m = m_lo + half * 8;
                float v0 = acc[mt][nt][half*2 + 0];
                float v1 = acc[mt][nt][half*2 + 1];
                if (mode == 1) {
                    float2 bi = *(const float2*)&bias[n];
                    *(float2*)&Cout[(size_t)m * DIMM + n] =
                        make_float2(v0 + bi.x, v1 + bi.y);
                } else {
                    int part = n >> 10, h = (n >> 6) & 15, d = n & 63;
                    int b = m >> 11, s = m & 2047;
                    int bh = b * NH + h;
                    if (part == 0) {          // Q: [qh | ql] fp16, pre-scaled
                        v0 *= 0.125f; v1 *= 0.125f;
                        uint32_t h2 = pack2h(v0, v1);
                        uint32_t l2 = pack2h(v0 - lo_h(h2), v1 - hi_h(h2));
                        size_t base = ((size_t)bh * SEQ + s) * 128 + d;
                        *(uint32_t*)&g_q[base]      = h2;
                        *(uint32_t*)&g_q[base + 64] = l2;
                    } else if (part == 1) {   // K: [kh | kh] fp16
                        uint32_t h2 = pack2h(v0, v1);
                        size_t base = ((size_t)bh * SEQ + s) * 128 + d;
                        *(uint32_t*)&g_k[base]      = h2;
                        *(uint32_t*)&g_k[base + 64] = h2;
                    } else {                  // V: single fp16 plane
                        uint32_t h2 = pack2h(v0, v1);
                        size_t base = ((size_t)bh * SEQ + s) * 64 + d;
                        *(uint32_t*)&g_v[base] = h2;
                    }
                }
            }
        }
    }
}

// ---------------- flash attention, fp16 2-term (d'=128, single V plane) ------
__global__ __launch_bounds__(256) void attn_mma_kernel()
{
    __shared__ __align__(16) __half Ks[64][136];
    __shared__ __align__(16) __half Vs[64][72];

    const int t    = threadIdx.x;
    const int wid  = t >> 5;
    const int lane = t & 31;
    const int bh   = blockIdx.y;
    const int q0   = blockIdx.x * 128;

    const __half* Qg = g_q + (size_t)bh * SEQ * 128;
    const __half* Kg = g_k + (size_t)bh * SEQ * 128;
    const __half* Vg = g_v + (size_t)bh * SEQ * 64;

    const uint32_t ksBase = smem_u32(&Ks[0][0]);
    const uint32_t vsBase = smem_u32(&Vs[0][0]);

    // ---- Q A-fragments directly from gmem (one-time; 8 k-steps) ----
    uint32_t qfr[8][4];
    {
        const __half* Qr = Qg + (size_t)(q0 + 16*wid + (lane >> 2)) * 128 + (lane & 3) * 2;
#pragma unroll
        for (int ks = 0; ks < 8; ks++) {
            qfr[ks][0] = *(const uint32_t*)(Qr + ks*16);
            qfr[ks][1] = *(const uint32_t*)(Qr + 8*128 + ks*16);
            qfr[ks][2] = *(const uint32_t*)(Qr + ks*16 + 8);
            qfr[ks][3] = *(const uint32_t*)(Qr + 8*128 + ks*16 + 8);
        }
    }

    float acc_o[8][4];
#pragma unroll
    for (int i = 0; i < 8; i++)
#pragma unroll
        for (int j = 0; j < 4; j++) acc_o[i][j] = 0.0f;
    float m_lo = -1e30f, m_hi = -1e30f, l_lo = 0.0f, l_hi = 0.0f;

    for (int j0 = 0; j0 < SEQ; j0 += 64) {
        __syncthreads();
#pragma unroll
        for (int i = 0; i < 4; i++) {
            int idx = t + i * 256;
            int r = idx >> 4, c = idx & 15;
            *(uint4*)&Ks[r][c*8] =
                *(const uint4*)(Kg + (size_t)(j0 + r) * 128 + c*8);
        }
#pragma unroll
        for (int i = 0; i < 2; i++) {
            int idx = t + i * 256;
            int r = idx >> 3, c = idx & 7;
            *(uint4*)&Vs[r][c*8] =
                *(const uint4*)(Vg + (size_t)(j0 + r) * 64 + c*8);
        }
        __syncthreads();

        // ---- S = Q' @ K'^T  (d'=128, 8 k-steps) ----
        float sc[8][4];
#pragma unroll
        for (int i = 0; i < 8; i++)
#pragma unroll
            for (int j = 0; j < 4; j++) sc[i][j] = 0.0f;

#pragma unroll
        for (int ks = 0; ks < 8; ks++) {
            const int k0 = ks * 16;
#pragma unroll
            for (int ntp = 0; ntp < 8; ntp += 2) {
                uint32_t tmp[4];
                ldsm_x4(tmp, ksBase +
                    (((ntp*8 + (lane >> 4)*8 + (lane & 7)) * 136)
                     + k0 + ((lane >> 3) & 1) * 8) * 2);
                mma_f16(sc[ntp],   qfr[ks], tmp);
                mma_f16(sc[ntp+1], qfr[ks], tmp + 2);
            }
        }

        // ---- online softmax (rows: lane>>2 and +8) ----
        float mx0 = -1e30f, mx1 = -1e30f;
#pragma unroll
        for (int nt = 0; nt < 8; nt++) {
            mx0 = fmaxf(mx0, fmaxf(sc[nt][0], sc[nt][1]));
            mx1 = fmaxf(mx1, fmaxf(sc[nt][2], sc[nt][3]));
        }
        mx0 = fmaxf(mx0, __shfl_xor_sync(0xffffffffu, mx0, 1));
        mx0 = fmaxf(mx0, __shfl_xor_sync(0xffffffffu, mx0, 2));
        mx1 = fmaxf(mx1, __shfl_xor_sync(0xffffffffu, mx1, 1));
        mx1 = fmaxf(mx1, __shfl_xor_sync(0xffffffffu, mx1, 2));
        float mn0 = fmaxf(m_lo, mx0), mn1 = fmaxf(m_hi, mx1);
        float f0 = __expf(m_lo - mn0), f1 = __expf(m_hi - mn1);
        m_lo = mn0; m_hi = mn1;

        float s0 = 0.0f, s1 = 0.0f;
#pragma unroll
        for (int nt = 0; nt < 8; nt++) {
            sc[nt][0] = __expf(sc[nt][0] - mn0); s0 += sc[nt][0];
            sc[nt][1] = __expf(sc[nt][1] - mn0); s0 += sc[nt][1];
            sc[nt][2] = __expf(sc[nt][2] - mn1); s1 += sc[nt][2];
            sc[nt][3] = __expf(sc[nt][3] - mn1); s1 += sc[nt][3];
        }
        s0 += __shfl_xor_sync(0xffffffffu, s0, 1);
        s0 += __shfl_xor_sync(0xffffffffu, s0, 2);
        s1 += __shfl_xor_sync(0xffffffffu, s1, 1);
        s1 += __shfl_xor_sync(0xffffffffu, s1, 2);
        l_lo = l_lo * f0 + s0;
        l_hi = l_hi * f1 + s1;
#pragma unroll
        for (int nt = 0; nt < 8; nt++) {
            acc_o[nt][0] *= f0; acc_o[nt][1] *= f0;
            acc_o[nt][2] *= f1; acc_o[nt][3] *= f1;
        }

        // ---- P fragments in fp16 hi/lo (C-layout == A-frag layout) ----
        uint32_t aph[4][4], apl[4][4];
#pragma unroll
        for (int kt = 0; kt < 4; kt++) {
            aph[kt][0] = pack2h(sc[2*kt][0],   sc[2*kt][1]);
            aph[kt][1] = pack2h(sc[2*kt][2],   sc[2*kt][3]);
            aph[kt][2] = pack2h(sc[2*kt+1][0], sc[2*kt+1][1]);
            aph[kt][3] = pack2h(sc[2*kt+1][2], sc[2*kt+1][3]);
            apl[kt][0] = pack2h(sc[2*kt][0]   - lo_h(aph[kt][0]), sc[2*kt][1]   - hi_h(aph[kt][0]));
            apl[kt][1] = pack2h(sc[2*kt][2]   - lo_h(aph[kt][1]), sc[2*kt][3]   - hi_h(aph[kt][1]));
            apl[kt][2] = pack2h(sc[2*kt+1][0] - lo_h(aph[kt][2]), sc[2*kt+1][1] - hi_h(aph[kt][2]));
            apl[kt][3] = pack2h(sc[2*kt+1][2] - lo_h(aph[kt][3]), sc[2*kt+1][3] - hi_h(aph[kt][3]));
        }

        // ---- O += P @ V   ((ph+pl)·vh; single V plane) ----
#pragma unroll
        for (int kt = 0; kt < 4; kt++) {
#pragma unroll
            for (int ntp = 0; ntp < 8; ntp += 2) {
                uint32_t vh4[4];
                uint32_t voff = (((kt*16 + (lane & 15)) * 72)
                                 + ntp*8 + (lane >> 4) * 8) * 2;
                ldsm_x4_t(vh4, vsBase + voff);
                mma_f16(acc_o[ntp],   aph[kt], vh4);
                mma_f16(acc_o[ntp],   apl[kt], vh4);
                mma_f16(acc_o[ntp+1], aph[kt], vh4 + 2);
                mma_f16(acc_o[ntp+1], apl[kt], vh4 + 2);
            }
        }
    }

    // ---- finalize: reference reshape semantics (flat view of [B,H,S,D]):
    //   (b,h,s,d) -> row b*2048 + h*128 + (s>>4), col (s&15)*64 + d
    float inv0 = 1.0f / l_lo, inv1 = 1.0f / l_hi;
    const int b = bh >> 4, h = bh & 15;
    const int s_base = q0 + 16*wid + (lane >> 2);
#pragma unroll
    for (int nt = 0; nt < 8; nt++) {
        int d = nt*8 + 2*(lane & 3);
#pragma unroll
        for (int half = 0; half < 2; half++) {
            int s = s_base + half * 8;
            int m   = b * 2048 + h * 128 + (s >> 4);
            int col = (s & 15) * 64 + d;
            float v0 = acc_o[nt][half*2 + 0] * (half ? inv1 : inv0);
            float v1 = acc_o[nt][half*2 + 1] * (half ? inv1 : inv0);
            uint32_t h2 = pack2h(v0, v1);
            uint32_t l2 = pack2h(v0 - lo_h(h2), v1 - hi_h(h2));
            size_t base = (size_t)m * GK + col;
            *(uint32_t*)&g_Ax[base]        = h2;
            *(uint32_t*)&g_Ax[base + 1024] = l2;
        }
    }
}

// ---------------------------------------------------------------------------
extern "C" void kernel_launch(void* const* d_in, const int* in_sizes, int n_in,
                              void* d_out, int out_size)
{
    const float* x     = (const float*)d_in[0];
    const float* w_qkv = (const float*)d_in[1];
    const float* w_out = (const float*)d_in[2];
    const float* b_out = (const float*)d_in[3];
    float* out = (float*)d_out;

    cudaFuncSetAttribute(mma_gemm_kernel<64>,
                         cudaFuncAttributeMaxDynamicSharedMemorySize, G_SMEM);
    cudaFuncSetAttribute(mma_gemm_kernel<32>,
                         cudaFuncAttributeMaxDynamicSharedMemorySize, G_SMEM);

    conv_split_kernel<<<MTOT, 256>>>(x);
    conv_w_kernel<<<dim3(32, 96), dim3(32, 32)>>>(w_qkv, 3072, 0);
    conv_w_kernel<<<dim3(32, 32), dim3(32, 32)>>>(w_out, 1024, 1);

    // GEMM1a: Q columns (n 0..1023), 2-term precision
    mma_gemm_kernel<64><<<dim3(8, MTOT/128), 256, G_SMEM>>>(nullptr, nullptr, 0, 0);
    // GEMM1b: K,V columns (n 1024..3071), 1-term (outputs get fp16-rounded anyway)
    mma_gemm_kernel<32><<<dim3(16, MTOT/128), 256, G_SMEM>>>(nullptr, nullptr, 0, 1024);

    // attention (writes fp16 GEMM2 input into g_Ax)
    attn_mma_kernel<<<dim3(SEQ/128, 64), 256>>>();

    // GEMM2: + bias -> out, 2-term
    mma_gemm_kernel<64><<<dim3(8, MTOT/128), 256, G_SMEM>>>(b_out, out, 1, 0);
}

// round 16
// speedup vs baseline: 3.5648x; 1.4965x over previous
#include <cuda_runtime.h>
#include <cuda_bf16.h>
#include <cuda_fp16.h>
#include <stdint.h>

#define SEQ   2048
#define BATCH 4
#define NH    16
#define HD    64
#define DIMM  1024
#define GK    2048          // doubled K for fp16 2-term compensated GEMM
#define MTOT  8192

typedef __nv_bfloat16 bf16;

// ---------------- scratch (__device__ globals; referenced ONLY in device code)
__device__ __half g_q   [(size_t)64*SEQ*64];     // [bh][s][qh] fp16, pre-scaled
__device__ __half g_k   [(size_t)64*SEQ*64];     // [bh][s][kh] fp16
__device__ __half g_v   [(size_t)64*SEQ*64];     // [bh][s][vh] fp16
__device__ __half g_Ax  [(size_t)MTOT*GK];       // fp16 [ah|al] activations
__device__ __half g_Bqkv[(size_t)3072*GK];       // fp16 [bh|bh] w_qkv^T
__device__ __half g_Bout[(size_t)1024*GK];       // fp16 [bh|bh] w_out^T

// ---------------- small helpers ---------------------------------------------
__device__ __forceinline__ uint32_t smem_u32(const void* p) {
    uint32_t a;
    asm("{ .reg .u64 t; cvta.to.shared.u64 t, %1; cvt.u32.u64 %0, t; }"
        : "=r"(a) : "l"(p));
    return a;
}
// fp16 pair pack: memory order [lo, hi]
__device__ __forceinline__ uint32_t pack2h(float lo, float hi) {
    uint32_t r;
    asm("cvt.rn.f16x2.f32 %0, %1, %2;" : "=r"(r) : "f"(hi), "f"(lo));
    return r;
}
__device__ __forceinline__ float lo_h(uint32_t x) {
    return __half2float(__ushort_as_half((unsigned short)(x & 0xffffu)));
}
__device__ __forceinline__ float hi_h(uint32_t x) {
    return __half2float(__ushort_as_half((unsigned short)(x >> 16)));
}

__device__ __forceinline__ void ldsm_x4(uint32_t* r, uint32_t addr) {
    asm volatile("ldmatrix.sync.aligned.m8n8.x4.shared.b16 {%0,%1,%2,%3}, [%4];"
        : "=r"(r[0]), "=r"(r[1]), "=r"(r[2]), "=r"(r[3]) : "r"(addr));
}
__device__ __forceinline__ void ldsm_x4_t(uint32_t* r, uint32_t addr) {
    asm volatile("ldmatrix.sync.aligned.m8n8.x4.trans.shared.b16 {%0,%1,%2,%3}, [%4];"
        : "=r"(r[0]), "=r"(r[1]), "=r"(r[2]), "=r"(r[3]) : "r"(addr));
}
__device__ __forceinline__ void mma_f16(float* d, const uint32_t* a, const uint32_t* b) {
    asm volatile(
        "mma.sync.aligned.m16n8k16.row.col.f32.f16.f16.f32 "
        "{%0,%1,%2,%3}, {%4,%5,%6,%7}, {%8,%9}, {%0,%1,%2,%3};"
        : "+f"(d[0]), "+f"(d[1]), "+f"(d[2]), "+f"(d[3])
        : "r"(a[0]), "r"(a[1]), "r"(a[2]), "r"(a[3]), "r"(b[0]), "r"(b[1]));
}
__device__ __forceinline__ void cp16(uint32_t s, const void* g) {
    asm volatile("cp.async.cg.shared.global [%0], [%1], 16;" :: "r"(s), "l"(g));
}
#define CP_COMMIT()  asm volatile("cp.async.commit_group;" ::: "memory")
#define CP_WAIT1()   asm volatile("cp.async.wait_group 1;" ::: "memory")
#define CP_WAIT0()   asm volatile("cp.async.wait_group 0;" ::: "memory")

__device__ __forceinline__ void split_f16(float v, __half& hi, __half& lo) {
    hi = __float2half_rn(v);
    lo = __float2half_rn(v - __half2float(hi));
}

// ---------------- conversion kernels ----------------------------------------
// x[m][0:1024] f32 -> g_Ax[m][0:2048] fp16 = [hi | lo]
__global__ __launch_bounds__(256) void conv_split_kernel(const float* __restrict__ in)
{
    int idx = blockIdx.x * 256 + threadIdx.x;
    int m  = idx >> 8;
    int c4 = (idx & 255) << 2;
    float4 v = *(const float4*)(in + (size_t)m * DIMM + c4);
    __half h[4], l[4];
    split_f16(v.x, h[0], l[0]); split_f16(v.y, h[1], l[1]);
    split_f16(v.z, h[2], l[2]); split_f16(v.w, h[3], l[3]);
    size_t ro = (size_t)m * GK + c4;
    *(uint2*)(g_Ax + ro)        = *(uint2*)h;
    *(uint2*)(g_Ax + ro + 1024) = *(uint2*)l;
}

// w[k][n] f32 -> B'[n][0:2048] fp16 = [hi | hi]  (transpose)
__global__ void conv_w_kernel(const float* __restrict__ w, int N, int which)
{
    __shared__ float tile[32][33];
    __half* outB = which ? g_Bout : g_Bqkv;
    int tx = threadIdx.x, ty = threadIdx.y;
    int k0 = blockIdx.x * 32, n0 = blockIdx.y * 32;
    tile[ty][tx] = w[(size_t)(k0 + ty) * N + n0 + tx];
    __syncthreads();
    float v = tile[tx][ty];
    int n = n0 + ty, k = k0 + tx;
    __half hi = __float2half_rn(v);
    size_t ro = (size_t)n * GK + k;
    outB[ro]        = hi;
    outB[ro + 1024] = hi;
}

// ---------------- mma.sync GEMM (fp16): 128x128, warp 64x32, BK=32 -----------
// NKBT = 64: 2-term (full K'); NKBT = 32: 1-term (hi halves only).
#define A_STG  10240                       // 128 x 40 fp16
#define G_SMEM (6 * A_STG)                 // 3 A stages + 3 B stages

template<int NKBT>
__global__ __launch_bounds__(256, 1) void mma_gemm_kernel(const float* __restrict__ bias,
                                                          float* __restrict__ Cout,
                                                          int mode, int noff)
{
    extern __shared__ __align__(16) char gsm[];
    const uint32_t aBase = smem_u32(gsm);
    const uint32_t bBase = aBase + 3 * A_STG;
    const uint32_t aS[3] = { aBase, aBase + A_STG, aBase + 2*A_STG };
    const uint32_t bS[3] = { bBase, bBase + A_STG, bBase + 2*A_STG };

    const __half* A = g_Ax;
    const __half* B = mode ? g_Bout : g_Bqkv;

    const int t    = threadIdx.x;
    const int wid  = t >> 5;
    const int lane = t & 31;
    const int warp_m = wid & 1;
    const int warp_n = wid >> 1;
    const int n0 = blockIdx.x * 128 + noff;
    const int m0 = blockIdx.y * 128;

    const int lrow = t >> 1;
    const int lseg = (t & 1) * 16;
    const __half* Ap = A + (size_t)(m0 + lrow) * GK + lseg;
    const __half* Bp = B + (size_t)(n0 + lrow) * GK + lseg;
    const uint32_t sOff = (uint32_t)(lrow * 40 + lseg) * 2;

    const uint32_t aLd = (uint32_t)(((warp_m*64 + (lane & 15)) * 40) + (lane >> 4) * 8) * 2;
    const uint32_t bLd = (uint32_t)(((warp_n*32 + (lane >> 4)*8 + (lane & 7)) * 40)
                                    + ((lane >> 3) & 1) * 8) * 2;

    float acc[4][4][4];
#pragma unroll
    for (int i = 0; i < 4; i++)
#pragma unroll
        for (int j = 0; j < 4; j++)
#pragma unroll
            for (int q = 0; q < 4; q++) acc[i][j][q] = 0.0f;

    uint32_t afr[2][4][4];
    uint32_t bfr[2][4][2];

    auto load_frags = [&](int buf, uint32_t ab, uint32_t bb, int k0) {
#pragma unroll
        for (int mt = 0; mt < 4; mt++)
            ldsm_x4(afr[buf][mt], ab + aLd + (uint32_t)(mt*16*40 + k0) * 2);
#pragma unroll
        for (int ntp = 0; ntp < 4; ntp += 2) {
            uint32_t tmp[4];
            ldsm_x4(tmp, bb + bLd + (uint32_t)(ntp*8*40 + k0) * 2);
            bfr[buf][ntp][0] = tmp[0];   bfr[buf][ntp][1] = tmp[1];
            bfr[buf][ntp+1][0] = tmp[2]; bfr[buf][ntp+1][1] = tmp[3];
        }
    };
    auto hmma_block = [&](int buf) {
#pragma unroll
        for (int mt = 0; mt < 4; mt++)
#pragma unroll
            for (int nt = 0; nt < 4; nt++)
                mma_f16(acc[mt][nt], afr[buf][mt], bfr[buf][nt]);
    };
    auto issue_cp = [&](int kb, int s) {
        const __half* Ak = Ap + kb * 32;
        const __half* Bk = Bp + kb * 32;
        cp16(aS[s] + sOff, Ak);  cp16(aS[s] + sOff + 16, Ak + 8);
        cp16(bS[s] + sOff, Bk);  cp16(bS[s] + sOff + 16, Bk + 8);
        CP_COMMIT();
    };

    issue_cp(0, 0);
    issue_cp(1, 1);
    CP_WAIT1();
    __syncthreads();
    load_frags(0, aS[0], bS[0], 0);

#define GSTEP(KB, S0, S1, S2) do {                                          \
        load_frags(1, aS[S0], bS[S0], 16);                                  \
        hmma_block(0);                                                      \
        if ((KB) + 2 < NKBT) issue_cp((KB) + 2, (S2));                      \
        hmma_block(1);                                                      \
        if ((KB) + 1 < NKBT) {                                              \
            if ((KB) + 2 < NKBT) CP_WAIT1(); else CP_WAIT0();               \
            __syncthreads();                                                \
            load_frags(0, aS[S1], bS[S1], 0);                               \
        }                                                                   \
    } while (0)

    constexpr int T3 = (NKBT / 3) * 3;
    for (int kb3 = 0; kb3 < T3; kb3 += 3) {
        GSTEP(kb3 + 0, 0, 1, 2);
        GSTEP(kb3 + 1, 1, 2, 0);
        GSTEP(kb3 + 2, 2, 0, 1);
    }
    if (NKBT % 3 >= 1) GSTEP(T3,     0, 1, 2);
    if (NKBT % 3 >= 2) GSTEP(T3 + 1, 1, 2, 0);
#undef GSTEP

    // ---------------- epilogue ----------------
#pragma unroll
    for (int mt = 0; mt < 4; mt++) {
#pragma unroll
        for (int nt = 0; nt < 4; nt++) {
            int m_lo = m0 + warp_m*64 + mt*16 + (lane >> 2);
            int n    = n0 + warp_n*32 + nt*8 + 2*(lane & 3);
#pragma unroll
            for (int half = 0; half < 2; half++) {
                int m = m_lo + half * 8;
                float v0 = acc[mt][nt][half*2 + 0];
                float v1 = acc[mt][nt][half*2 + 1];
                if (mode == 1) {
                    float2 bi = *(const float2*)&bias[n];
                    *(float2*)&Cout[(size_t)m * DIMM + n] =
                        make_float2(v0 + bi.x, v1 + bi.y);
                } else {
                    int part = n >> 10, h = (n >> 6) & 15, d = n & 63;
                    int b = m >> 11, s = m & 2047;
                    int bh = b * NH + h;
                    if (part == 0) { v0 *= 0.125f; v1 *= 0.125f; }
                    uint32_t h2 = pack2h(v0, v1);
                    __half* dst = (part == 0) ? g_q : (part == 1) ? g_k : g_v;
                    size_t base = ((size_t)bh * SEQ + s) * 64 + d;
                    *(uint32_t*)&dst[base] = h2;
                }
            }
        }
    }
}

// ---------------- flash attention, plain fp16 (d=64, 1-term everywhere) ------
// O accumulated fp32; epilogue emits 2-term [oh|ol] for GEMM2.
__global__ __launch_bounds__(256) void attn_mma_kernel()
{
    __shared__ __align__(16) __half Ks[64][72];
    __shared__ __align__(16) __half Vs[64][72];

    const int t    = threadIdx.x;
    const int wid  = t >> 5;
    const int lane = t & 31;
    const int bh   = blockIdx.y;
    const int q0   = blockIdx.x * 128;

    const __half* Qg = g_q + (size_t)bh * SEQ * 64;
    const __half* Kg = g_k + (size_t)bh * SEQ * 64;
    const __half* Vg = g_v + (size_t)bh * SEQ * 64;

    const uint32_t ksBase = smem_u32(&Ks[0][0]);
    const uint32_t vsBase = smem_u32(&Vs[0][0]);

    // ---- Q A-fragments directly from gmem (one-time; 4 k-steps over d=64) ---
    uint32_t qfr[4][4];
    {
        const __half* Qr = Qg + (size_t)(q0 + 16*wid + (lane >> 2)) * 64 + (lane & 3) * 2;
#pragma unroll
        for (int ks = 0; ks < 4; ks++) {
            qfr[ks][0] = *(const uint32_t*)(Qr + ks*16);
            qfr[ks][1] = *(const uint32_t*)(Qr + 8*64 + ks*16);
            qfr[ks][2] = *(const uint32_t*)(Qr + ks*16 + 8);
            qfr[ks][3] = *(const uint32_t*)(Qr + 8*64 + ks*16 + 8);
        }
    }

    float acc_o[8][4];
#pragma unroll
    for (int i = 0; i < 8; i++)
#pragma unroll
        for (int j = 0; j < 4; j++) acc_o[i][j] = 0.0f;
    float m_lo = -1e30f, m_hi = -1e30f, l_lo = 0.0f, l_hi = 0.0f;

    for (int j0 = 0; j0 < SEQ; j0 += 64) {
        __syncthreads();
        // K tile 64x64 fp16 (stride 72), V tile 64x64 fp16 (stride 72)
#pragma unroll
        for (int i = 0; i < 2; i++) {
            int idx = t + i * 256;        // 512 chunks of 8 fp16
            int r = idx >> 3, c = idx & 7;
            *(uint4*)&Ks[r][c*8] =
                *(const uint4*)(Kg + (size_t)(j0 + r) * 64 + c*8);
            *(uint4*)&Vs[r][c*8] =
                *(const uint4*)(Vg + (size_t)(j0 + r) * 64 + c*8);
        }
        __syncthreads();

        // ---- S = Q @ K^T  (d=64, 4 k-steps) ----
        float sc[8][4];
#pragma unroll
        for (int i = 0; i < 8; i++)
#pragma unroll
            for (int j = 0; j < 4; j++) sc[i][j] = 0.0f;

#pragma unroll
        for (int ks = 0; ks < 4; ks++) {
            const int k0 = ks * 16;
#pragma unroll
            for (int ntp = 0; ntp < 8; ntp += 2) {
                uint32_t tmp[4];
                ldsm_x4(tmp, ksBase +
                    (((ntp*8 + (lane >> 4)*8 + (lane & 7)) * 72)
                     + k0 + ((lane >> 3) & 1) * 8) * 2);
                mma_f16(sc[ntp],   qfr[ks], tmp);
                mma_f16(sc[ntp+1], qfr[ks], tmp + 2);
            }
        }

        // ---- online softmax (rows: lane>>2 and +8) ----
        float mx0 = -1e30f, mx1 = -1e30f;
#pragma unroll
        for (int nt = 0; nt < 8; nt++) {
            mx0 = fmaxf(mx0, fmaxf(sc[nt][0], sc[nt][1]));
            mx1 = fmaxf(mx1, fmaxf(sc[nt][2], sc[nt][3]));
        }
        mx0 = fmaxf(mx0, __shfl_xor_sync(0xffffffffu, mx0, 1));
        mx0 = fmaxf(mx0, __shfl_xor_sync(0xffffffffu, mx0, 2));
        mx1 = fmaxf(mx1, __shfl_xor_sync(0xffffffffu, mx1, 1));
        mx1 = fmaxf(mx1, __shfl_xor_sync(0xffffffffu, mx1, 2));
        float mn0 = fmaxf(m_lo, mx0), mn1 = fmaxf(m_hi, mx1);
        float f0 = __expf(m_lo - mn0), f1 = __expf(m_hi - mn1);
        m_lo = mn0; m_hi = mn1;

        float s0 = 0.0f, s1 = 0.0f;
#pragma unroll
        for (int nt = 0; nt < 8; nt++) {
            sc[nt][0] = __expf(sc[nt][0] - mn0); s0 += sc[nt][0];
            sc[nt][1] = __expf(sc[nt][1] - mn0); s0 += sc[nt][1];
            sc[nt][2] = __expf(sc[nt][2] - mn1); s1 += sc[nt][2];
            sc[nt][3] = __expf(sc[nt][3] - mn1); s1 += sc[nt][3];
        }
        s0 += __shfl_xor_sync(0xffffffffu, s0, 1);
        s0 += __shfl_xor_sync(0xffffffffu, s0, 2);
        s1 += __shfl_xor_sync(0xffffffffu, s1, 1);
        s1 += __shfl_xor_sync(0xffffffffu, s1, 2);
        l_lo = l_lo * f0 + s0;
        l_hi = l_hi * f1 + s1;
#pragma unroll
        for (int nt = 0; nt < 8; nt++) {
            acc_o[nt][0] *= f0; acc_o[nt][1] *= f0;
            acc_o[nt][2] *= f1; acc_o[nt][3] *= f1;
        }

        // ---- P fragments fp16 (C-layout == A-frag layout) ----
        uint32_t aph[4][4];
#pragma unroll
        for (int kt = 0; kt < 4; kt++) {
            aph[kt][0] = pack2h(sc[2*kt][0],   sc[2*kt][1]);
            aph[kt][1] = pack2h(sc[2*kt][2],   sc[2*kt][3]);
            aph[kt][2] = pack2h(sc[2*kt+1][0], sc[2*kt+1][1]);
            aph[kt][3] = pack2h(sc[2*kt+1][2], sc[2*kt+1][3]);
        }

        // ---- O += P @ V ----
#pragma unroll
        for (int kt = 0; kt < 4; kt++) {
#pragma unroll
            for (int ntp = 0; ntp < 8; ntp += 2) {
                uint32_t vh4[4];
                uint32_t voff = (((kt*16 + (lane & 15)) * 72)
                                 + ntp*8 + (lane >> 4) * 8) * 2;
                ldsm_x4_t(vh4, vsBase + voff);
                mma_f16(acc_o[ntp],   aph[kt], vh4);
                mma_f16(acc_o[ntp+1], aph[kt], vh4 + 2);
            }
        }
    }

    // ---- finalize: reference reshape semantics (flat view of [B,H,S,D]):
    //   (b,h,s,d) -> row b*2048 + h*128 + (s>>4), col (s&15)*64 + d
    //   Emit fp16 [hi | lo] GEMM2 operand.
    float inv0 = 1.0f / l_lo, inv1 = 1.0f / l_hi;
    const int b = bh >> 4, h = bh & 15;
    const int s_base = q0 + 16*wid + (lane >> 2);
#pragma unroll
    for (int nt = 0; nt < 8; nt++) {
        int d = nt*8 + 2*(lane & 3);
#pragma unroll
        for (int half = 0; half < 2; half++) {
            int s = s_base + half * 8;
            int m   = b * 2048 + h * 128 + (s >> 4);
            int col = (s & 15) * 64 + d;
            float v0 = acc_o[nt][half*2 + 0] * (half ? inv1 : inv0);
            float v1 = acc_o[nt][half*2 + 1] * (half ? inv1 : inv0);
            uint32_t h2 = pack2h(v0, v1);
            uint32_t l2 = pack2h(v0 - lo_h(h2), v1 - hi_h(h2));
            size_t base = (size_t)m * GK + col;
            *(uint32_t*)&g_Ax[base]        = h2;
            *(uint32_t*)&g_Ax[base + 1024] = l2;
        }
    }
}

// ---------------------------------------------------------------------------
extern "C" void kernel_launch(void* const* d_in, const int* in_sizes, int n_in,
                              void* d_out, int out_size)
{
    const float* x     = (const float*)d_in[0];
    const float* w_qkv = (const float*)d_in[1];
    const float* w_out = (const float*)d_in[2];
    const float* b_out = (const float*)d_in[3];
    float* out = (float*)d_out;

    cudaFuncSetAttribute(mma_gemm_kernel<64>,
                         cudaFuncAttributeMaxDynamicSharedMemorySize, G_SMEM);
    cudaFuncSetAttribute(mma_gemm_kernel<32>,
                         cudaFuncAttributeMaxDynamicSharedMemorySize, G_SMEM);

    conv_split_kernel<<<MTOT, 256>>>(x);
    conv_w_kernel<<<dim3(32, 96), dim3(32, 32)>>>(w_qkv, 3072, 0);
    conv_w_kernel<<<dim3(32, 32), dim3(32, 32)>>>(w_out, 1024, 1);

    // GEMM1: all q/k/v columns, 1-term fp16 (outputs get fp16-rounded anyway)
    mma_gemm_kernel<32><<<dim3(24, MTOT/128), 256, G_SMEM>>>(nullptr, nullptr, 0, 0);

    // attention (writes fp16 2-term GEMM2 input into g_Ax)
    attn_mma_kernel<<<dim3(SEQ/128, 64), 256>>>();

    // GEMM2: + bias -> out, 2-term (final fp32 output precision)
    mma_gemm_kernel<64><<<dim3(8, MTOT/128), 256, G_SMEM>>>(b_out, out, 1, 0);
}

// round 17
// speedup vs baseline: 4.0675x; 1.1410x over previous
#include <cuda_runtime.h>
#include <cuda_bf16.h>
#include <cuda_fp16.h>
#include <stdint.h>

#define SEQ   2048
#define BATCH 4
#define NH    16
#define HD    64
#define DIMM  1024
#define GK    1024          // plain fp16 1-term everywhere
#define MTOT  8192
#define NKB   (GK/32)       // 32 k-blocks of 32

typedef __nv_bfloat16 bf16;

// ---------------- scratch (__device__ globals; referenced ONLY in device code)
__device__ __half g_q   [(size_t)64*SEQ*64];     // [bh][s][qh] fp16, pre-scaled
__device__ __half g_k   [(size_t)64*SEQ*64];     // [bh][s][kh] fp16
__device__ __half g_v   [(size_t)64*SEQ*64];     // [bh][s][vh] fp16
__device__ __half g_Ax  [(size_t)MTOT*GK];       // fp16 activations (x, later attn out)
__device__ __half g_Bqkv[(size_t)3072*GK];       // fp16 w_qkv^T
__device__ __half g_Bout[(size_t)1024*GK];       // fp16 w_out^T

// ---------------- small helpers ---------------------------------------------
__device__ __forceinline__ uint32_t smem_u32(const void* p) {
    uint32_t a;
    asm("{ .reg .u64 t; cvta.to.shared.u64 t, %1; cvt.u32.u64 %0, t; }"
        : "=r"(a) : "l"(p));
    return a;
}
// fp16 pair pack: memory order [lo, hi]
__device__ __forceinline__ uint32_t pack2h(float lo, float hi) {
    uint32_t r;
    asm("cvt.rn.f16x2.f32 %0, %1, %2;" : "=r"(r) : "f"(hi), "f"(lo));
    return r;
}

__device__ __forceinline__ void ldsm_x4(uint32_t* r, uint32_t addr) {
    asm volatile("ldmatrix.sync.aligned.m8n8.x4.shared.b16 {%0,%1,%2,%3}, [%4];"
        : "=r"(r[0]), "=r"(r[1]), "=r"(r[2]), "=r"(r[3]) : "r"(addr));
}
__device__ __forceinline__ void ldsm_x4_t(uint32_t* r, uint32_t addr) {
    asm volatile("ldmatrix.sync.aligned.m8n8.x4.trans.shared.b16 {%0,%1,%2,%3}, [%4];"
        : "=r"(r[0]), "=r"(r[1]), "=r"(r[2]), "=r"(r[3]) : "r"(addr));
}
__device__ __forceinline__ void mma_f16(float* d, const uint32_t* a, const uint32_t* b) {
    asm volatile(
        "mma.sync.aligned.m16n8k16.row.col.f32.f16.f16.f32 "
        "{%0,%1,%2,%3}, {%4,%5,%6,%7}, {%8,%9}, {%0,%1,%2,%3};"
        : "+f"(d[0]), "+f"(d[1]), "+f"(d[2]), "+f"(d[3])
        : "r"(a[0]), "r"(a[1]), "r"(a[2]), "r"(a[3]), "r"(b[0]), "r"(b[1]));
}
__device__ __forceinline__ void cp16(uint32_t s, const void* g) {
    asm volatile("cp.async.cg.shared.global [%0], [%1], 16;" :: "r"(s), "l"(g));
}
#define CP_COMMIT()  asm volatile("cp.async.commit_group;" ::: "memory")
#define CP_WAIT1()   asm volatile("cp.async.wait_group 1;" ::: "memory")
#define CP_WAIT0()   asm volatile("cp.async.wait_group 0;" ::: "memory")

// ---------------- conversion kernels ----------------------------------------
// x[m][0:1024] f32 -> g_Ax[m][0:1024] fp16
__global__ __launch_bounds__(256) void conv_split_kernel(const float* __restrict__ in)
{
    int idx = blockIdx.x * 256 + threadIdx.x;
    int m  = idx >> 8;
    int c4 = (idx & 255) << 2;
    float4 v = *(const float4*)(in + (size_t)m * DIMM + c4);
    __half h[4];
    h[0] = __float2half_rn(v.x); h[1] = __float2half_rn(v.y);
    h[2] = __float2half_rn(v.z); h[3] = __float2half_rn(v.w);
    *(uint2*)(g_Ax + (size_t)m * GK + c4) = *(uint2*)h;
}

// w[k][n] f32 -> B'[n][0:1024] fp16  (transpose)
__global__ void conv_w_kernel(const float* __restrict__ w, int N, int which)
{
    __shared__ float tile[32][33];
    __half* outB = which ? g_Bout : g_Bqkv;
    int tx = threadIdx.x, ty = threadIdx.y;
    int k0 = blockIdx.x * 32, n0 = blockIdx.y * 32;
    tile[ty][tx] = w[(size_t)(k0 + ty) * N + n0 + tx];
    __syncthreads();
    float v = tile[tx][ty];
    int n = n0 + ty, k = k0 + tx;
    outB[(size_t)n * GK + k] = __float2half_rn(v);
}

// ---------------- mma.sync GEMM (fp16 1-term): 128x128, warp 64x32, BK=32 ----
#define A_STG  10240                       // 128 x 40 fp16
#define G_SMEM (6 * A_STG)                 // 3 A stages + 3 B stages

__global__ __launch_bounds__(256, 1) void mma_gemm_kernel(const float* __restrict__ bias,
                                                          float* __restrict__ Cout,
                                                          int mode)
{
    extern __shared__ __align__(16) char gsm[];
    const uint32_t aBase = smem_u32(gsm);
    const uint32_t bBase = aBase + 3 * A_STG;
    const uint32_t aS[3] = { aBase, aBase + A_STG, aBase + 2*A_STG };
    const uint32_t bS[3] = { bBase, bBase + A_STG, bBase + 2*A_STG };

    const __half* A = g_Ax;
    const __half* B = mode ? g_Bout : g_Bqkv;

    const int t    = threadIdx.x;
    const int wid  = t >> 5;
    const int lane = t & 31;
    const int warp_m = wid & 1;
    const int warp_n = wid >> 1;
    const int n0 = blockIdx.x * 128;
    const int m0 = blockIdx.y * 128;

    const int lrow = t >> 1;
    const int lseg = (t & 1) * 16;
    const __half* Ap = A + (size_t)(m0 + lrow) * GK + lseg;
    const __half* Bp = B + (size_t)(n0 + lrow) * GK + lseg;
    const uint32_t sOff = (uint32_t)(lrow * 40 + lseg) * 2;

    const uint32_t aLd = (uint32_t)(((warp_m*64 + (lane & 15)) * 40) + (lane >> 4) * 8) * 2;
    const uint32_t bLd = (uint32_t)(((warp_n*32 + (lane >> 4)*8 + (lane & 7)) * 40)
                                    + ((lane >> 3) & 1) * 8) * 2;

    float acc[4][4][4];
#pragma unroll
    for (int i = 0; i < 4; i++)
#pragma unroll
        for (int j = 0; j < 4; j++)
#pragma unroll
            for (int q = 0; q < 4; q++) acc[i][j][q] = 0.0f;

    uint32_t afr[2][4][4];
    uint32_t bfr[2][4][2];

    auto load_frags = [&](int buf, uint32_t ab, uint32_t bb, int k0) {
#pragma unroll
        for (int mt = 0; mt < 4; mt++)
            ldsm_x4(afr[buf][mt], ab + aLd + (uint32_t)(mt*16*40 + k0) * 2);
#pragma unroll
        for (int ntp = 0; ntp < 4; ntp += 2) {
            uint32_t tmp[4];
            ldsm_x4(tmp, bb + bLd + (uint32_t)(ntp*8*40 + k0) * 2);
            bfr[buf][ntp][0] = tmp[0];   bfr[buf][ntp][1] = tmp[1];
            bfr[buf][ntp+1][0] = tmp[2]; bfr[buf][ntp+1][1] = tmp[3];
        }
    };
    auto hmma_block = [&](int buf) {
#pragma unroll
        for (int mt = 0; mt < 4; mt++)
#pragma unroll
            for (int nt = 0; nt < 4; nt++)
                mma_f16(acc[mt][nt], afr[buf][mt], bfr[buf][nt]);
    };
    auto issue_cp = [&](int kb, int s) {
        const __half* Ak = Ap + kb * 32;
        const __half* Bk = Bp + kb * 32;
        cp16(aS[s] + sOff, Ak);  cp16(aS[s] + sOff + 16, Ak + 8);
        cp16(bS[s] + sOff, Bk);  cp16(bS[s] + sOff + 16, Bk + 8);
        CP_COMMIT();
    };

    issue_cp(0, 0);
    issue_cp(1, 1);
    CP_WAIT1();
    __syncthreads();
    load_frags(0, aS[0], bS[0], 0);

#define GSTEP(KB, S0, S1, S2) do {                                          \
        load_frags(1, aS[S0], bS[S0], 16);                                  \
        hmma_block(0);                                                      \
        if ((KB) + 2 < NKB) issue_cp((KB) + 2, (S2));                       \
        hmma_block(1);                                                      \
        if ((KB) + 1 < NKB) {                                               \
            if ((KB) + 2 < NKB) CP_WAIT1(); else CP_WAIT0();                \
            __syncthreads();                                                \
            load_frags(0, aS[S1], bS[S1], 0);                               \
        }                                                                   \
    } while (0)

    // NKB = 32 = 3*10 + 2
    for (int kb3 = 0; kb3 < 30; kb3 += 3) {
        GSTEP(kb3 + 0, 0, 1, 2);
        GSTEP(kb3 + 1, 1, 2, 0);
        GSTEP(kb3 + 2, 2, 0, 1);
    }
    GSTEP(30, 0, 1, 2);
    GSTEP(31, 1, 2, 0);
#undef GSTEP

    // ---------------- epilogue ----------------
#pragma unroll
    for (int mt = 0; mt < 4; mt++) {
#pragma unroll
        for (int nt = 0; nt < 4; nt++) {
            int m_lo = m0 + warp_m*64 + mt*16 + (lane >> 2);
            int n    = n0 + warp_n*32 + nt*8 + 2*(lane & 3);
#pragma unroll
            for (int half = 0; half < 2; half++) {
                int m = m_lo + half * 8;
                float v0 = acc[mt][nt][half*2 + 0];
                float v1 = acc[mt][nt][half*2 + 1];
                if (mode == 1) {
                    float2 bi = *(const float2*)&bias[n];
                    *(float2*)&Cout[(size_t)m * DIMM + n] =
                        make_float2(v0 + bi.x, v1 + bi.y);
                } else {
                    int part = n >> 10, h = (n >> 6) & 15, d = n & 63;
                    int b = m >> 11, s = m & 2047;
                    int bh = b * NH + h;
                    if (part == 0) { v0 *= 0.125f; v1 *= 0.125f; }
                    uint32_t h2 = pack2h(v0, v1);
                    __half* dst = (part == 0) ? g_q : (part == 1) ? g_k : g_v;
                    size_t base = ((size_t)bh * SEQ + s) * 64 + d;
                    *(uint32_t*)&dst[base] = h2;
                }
            }
        }
    }
}

// ---------------- flash attention, plain fp16 (d=64) -------------------------
__global__ __launch_bounds__(256) void attn_mma_kernel()
{
    __shared__ __align__(16) __half Ks[64][72];
    __shared__ __align__(16) __half Vs[64][72];

    const int t    = threadIdx.x;
    const int wid  = t >> 5;
    const int lane = t & 31;
    const int bh   = blockIdx.y;
    const int q0   = blockIdx.x * 128;

    const __half* Qg = g_q + (size_t)bh * SEQ * 64;
    const __half* Kg = g_k + (size_t)bh * SEQ * 64;
    const __half* Vg = g_v + (size_t)bh * SEQ * 64;

    const uint32_t ksBase = smem_u32(&Ks[0][0]);
    const uint32_t vsBase = smem_u32(&Vs[0][0]);

    // ---- Q A-fragments directly from gmem (one-time; 4 k-steps over d=64) ---
    uint32_t qfr[4][4];
    {
        const __half* Qr = Qg + (size_t)(q0 + 16*wid + (lane >> 2)) * 64 + (lane & 3) * 2;
#pragma unroll
        for (int ks = 0; ks < 4; ks++) {
            qfr[ks][0] = *(const uint32_t*)(Qr + ks*16);
            qfr[ks][1] = *(const uint32_t*)(Qr + 8*64 + ks*16);
            qfr[ks][2] = *(const uint32_t*)(Qr + ks*16 + 8);
            qfr[ks][3] = *(const uint32_t*)(Qr + 8*64 + ks*16 + 8);
        }
    }

    float acc_o[8][4];
#pragma unroll
    for (int i = 0; i < 8; i++)
#pragma unroll
        for (int j = 0; j < 4; j++) acc_o[i][j] = 0.0f;
    float m_lo = -1e30f, m_hi = -1e30f, l_lo = 0.0f, l_hi = 0.0f;

    for (int j0 = 0; j0 < SEQ; j0 += 64) {
        __syncthreads();
#pragma unroll
        for (int i = 0; i < 2; i++) {
            int idx = t + i * 256;        // 512 chunks of 8 fp16
            int r = idx >> 3, c = idx & 7;
            *(uint4*)&Ks[r][c*8] =
                *(const uint4*)(Kg + (size_t)(j0 + r) * 64 + c*8);
            *(uint4*)&Vs[r][c*8] =
                *(const uint4*)(Vg + (size_t)(j0 + r) * 64 + c*8);
        }
        __syncthreads();

        // ---- S = Q @ K^T  (d=64, 4 k-steps) ----
        float sc[8][4];
#pragma unroll
        for (int i = 0; i < 8; i++)
#pragma unroll
            for (int j = 0; j < 4; j++) sc[i][j] = 0.0f;

#pragma unroll
        for (int ks = 0; ks < 4; ks++) {
            const int k0 = ks * 16;
#pragma unroll
            for (int ntp = 0; ntp < 8; ntp += 2) {
                uint32_t tmp[4];
                ldsm_x4(tmp, ksBase +
                    (((ntp*8 + (lane >> 4)*8 + (lane & 7)) * 72)
                     + k0 + ((lane >> 3) & 1) * 8) * 2);
                mma_f16(sc[ntp],   qfr[ks], tmp);
                mma_f16(sc[ntp+1], qfr[ks], tmp + 2);
            }
        }

        // ---- online softmax (rows: lane>>2 and +8) ----
        float mx0 = -1e30f, mx1 = -1e30f;
#pragma unroll
        for (int nt = 0; nt < 8; nt++) {
            mx0 = fmaxf(mx0, fmaxf(sc[nt][0], sc[nt][1]));
            mx1 = fmaxf(mx1, fmaxf(sc[nt][2], sc[nt][3]));
        }
        mx0 = fmaxf(mx0, __shfl_xor_sync(0xffffffffu, mx0, 1));
        mx0 = fmaxf(mx0, __shfl_xor_sync(0xffffffffu, mx0, 2));
        mx1 = fmaxf(mx1, __shfl_xor_sync(0xffffffffu, mx1, 1));
        mx1 = fmaxf(mx1, __shfl_xor_sync(0xffffffffu, mx1, 2));
        float mn0 = fmaxf(m_lo, mx0), mn1 = fmaxf(m_hi, mx1);
        float f0 = __expf(m_lo - mn0), f1 = __expf(m_hi - mn1);
        m_lo = mn0; m_hi = mn1;

        float s0 = 0.0f, s1 = 0.0f;
#pragma unroll
        for (int nt = 0; nt < 8; nt++) {
            sc[nt][0] = __expf(sc[nt][0] - mn0); s0 += sc[nt][0];
            sc[nt][1] = __expf(sc[nt][1] - mn0); s0 += sc[nt][1];
            sc[nt][2] = __expf(sc[nt][2] - mn1); s1 += sc[nt][2];
            sc[nt][3] = __expf(sc[nt][3] - mn1); s1 += sc[nt][3];
        }
        s0 += __shfl_xor_sync(0xffffffffu, s0, 1);
        s0 += __shfl_xor_sync(0xffffffffu, s0, 2);
        s1 += __shfl_xor_sync(0xffffffffu, s1, 1);
        s1 += __shfl_xor_sync(0xffffffffu, s1, 2);
        l_lo = l_lo * f0 + s0;
        l_hi = l_hi * f1 + s1;
#pragma unroll
        for (int nt = 0; nt < 8; nt++) {
            acc_o[nt][0] *= f0; acc_o[nt][1] *= f0;
            acc_o[nt][2] *= f1; acc_o[nt][3] *= f1;
        }

        // ---- P fragments fp16 (C-layout == A-frag layout) ----
        uint32_t aph[4][4];
#pragma unroll
        for (int kt = 0; kt < 4; kt++) {
            aph[kt][0] = pack2h(sc[2*kt][0],   sc[2*kt][1]);
            aph[kt][1] = pack2h(sc[2*kt][2],   sc[2*kt][3]);
            aph[kt][2] = pack2h(sc[2*kt+1][0], sc[2*kt+1][1]);
            aph[kt][3] = pack2h(sc[2*kt+1][2], sc[2*kt+1][3]);
        }

        // ---- O += P @ V ----
#pragma unroll
        for (int kt = 0; kt < 4; kt++) {
#pragma unroll
            for (int ntp = 0; ntp < 8; ntp += 2) {
                uint32_t vh4[4];
                uint32_t voff = (((kt*16 + (lane & 15)) * 72)
                                 + ntp*8 + (lane >> 4) * 8) * 2;
                ldsm_x4_t(vh4, vsBase + voff);
                mma_f16(acc_o[ntp],   aph[kt], vh4);
                mma_f16(acc_o[ntp+1], aph[kt], vh4 + 2);
            }
        }
    }

    // ---- finalize: reference reshape semantics (flat view of [B,H,S,D]):
    //   (b,h,s,d) -> row b*2048 + h*128 + (s>>4), col (s&15)*64 + d
    float inv0 = 1.0f / l_lo, inv1 = 1.0f / l_hi;
    const int b = bh >> 4, h = bh & 15;
    const int s_base = q0 + 16*wid + (lane >> 2);
#pragma unroll
    for (int nt = 0; nt < 8; nt++) {
        int d = nt*8 + 2*(lane & 3);
#pragma unroll
        for (int half = 0; half < 2; half++) {
            int s = s_base + half * 8;
            int m   = b * 2048 + h * 128 + (s >> 4);
            int col = (s & 15) * 64 + d;
            float v0 = acc_o[nt][half*2 + 0] * (half ? inv1 : inv0);
            float v1 = acc_o[nt][half*2 + 1] * (half ? inv1 : inv0);
            *(uint32_t*)&g_Ax[(size_t)m * GK + col] = pack2h(v0, v1);
        }
    }
}

// ---------------------------------------------------------------------------
extern "C" void kernel_launch(void* const* d_in, const int* in_sizes, int n_in,
                              void* d_out, int out_size)
{
    const float* x     = (const float*)d_in[0];
    const float* w_qkv = (const float*)d_in[1];
    const float* w_out = (const float*)d_in[2];
    const float* b_out = (const float*)d_in[3];
    float* out = (float*)d_out;

    cudaFuncSetAttribute(mma_gemm_kernel,
                         cudaFuncAttributeMaxDynamicSharedMemorySize, G_SMEM);

    conv_split_kernel<<<MTOT, 256>>>(x);
    conv_w_kernel<<<dim3(32, 96), dim3(32, 32)>>>(w_qkv, 3072, 0);
    conv_w_kernel<<<dim3(32, 32), dim3(32, 32)>>>(w_out, 1024, 1);

    // GEMM1: qkv (fp16 1-term)
    mma_gemm_kernel<<<dim3(24, MTOT/128), 256, G_SMEM>>>(nullptr, nullptr, 0);

    // attention (writes fp16 GEMM2 input into g_Ax)
    attn_mma_kernel<<<dim3(SEQ/128, 64), 256>>>();

    // GEMM2: + bias -> out (fp16 1-term)
    mma_gemm_kernel<<<dim3(8, MTOT/128), 256, G_SMEM>>>(b_out, out, 1);
}